// round 8
// baseline (speedup 1.0000x reference)
#include <cuda_runtime.h>
#include <cuda_bf16.h>
#include <math.h>
#include <cstdint>

#define NN 100000
#define EE 400000
#define GG 64

// ---------------- scratch (device globals; no allocation allowed) ----------------
__device__ float g_h0[NN * 64];        // encoder output (tf32-rounded values)
__device__ float g_xl[NN * 256];       // source-side transform
__device__ float g_xr[NN * 256];       // target-side transform
__device__ float g_h1[NN * 256];       // layer output (tf32-rounded after layer 1)
__device__ float g_sums[GG * 256];     // pooled sums (zeroed by head_kernel after use)
__device__ float g_cnt[GG];            // node counts (zeroed by head_kernel after use)
__device__ float g_wt[512 * 256];      // fused transposed weights [512 n-rows, K] (tf32-rounded)
// CSR over dst (built once per launch; dst shared by both layers)
__device__ int   g_rowptr[NN + 1];
__device__ int   g_cnts[NN];           // histogram (self-cleared by scan1 each run)
__device__ int   g_cursor[NN];         // write cursors (seeded by scan3 each run)
__device__ int   g_csrc[EE];           // src id per CSR slot
__device__ float g_cea[EE];            // edge attr per CSR slot
__device__ int   g_bsums[128];

// ---------------- small utils ----------------
__device__ __forceinline__ uint32_t cvt_tf32(float x) {
    uint32_t r;
    asm("cvt.rna.tf32.f32 %0, %1;" : "=r"(r) : "f"(x));
    return r;
}
__device__ __forceinline__ float round_tf32(float x) {
    return __uint_as_float(cvt_tf32(x));
}
__device__ __forceinline__ uint32_t smem_u32(const void* p) {
    uint32_t a;
    asm("{ .reg .u64 t; cvta.to.shared.u64 t, %1; cvt.u32.u64 %0, t; }" : "=r"(a) : "l"(p));
    return a;
}
__device__ __forceinline__ void cp16(uint32_t saddr, const void* g, bool pred) {
    int sz = pred ? 16 : 0;
    asm volatile("cp.async.cg.shared.global [%0], [%1], 16, %2;"
                 :: "r"(saddr), "l"(g), "r"(sz));
}
__device__ __forceinline__ void mma_tf32_16x8x8(float* d, const uint32_t* a, const uint32_t* b) {
    asm volatile(
        "mma.sync.aligned.m16n8k8.row.col.f32.tf32.tf32.f32 "
        "{%0,%1,%2,%3}, {%4,%5,%6,%7}, {%8,%9}, {%0,%1,%2,%3};"
        : "+f"(d[0]), "+f"(d[1]), "+f"(d[2]), "+f"(d[3])
        : "r"(a[0]), "r"(a[1]), "r"(a[2]), "r"(a[3]), "r"(b[0]), "r"(b[1]));
}

// ---------------- CSR build over dst ----------------
__global__ void hist_kernel(const int* __restrict__ dst, int* __restrict__ cnts) {
    int e = blockIdx.x * blockDim.x + threadIdx.x;
    if (e < EE) atomicAdd(&cnts[dst[e]], 1);
}
__global__ void scan1_kernel(int* __restrict__ cnts, int* __restrict__ rowptr,
                             int* __restrict__ bsums) {
    __shared__ int buf[2][1024];
    int b = blockIdx.x, t = threadIdx.x;
    int i = b * 1024 + t;
    int myc = (i < NN) ? cnts[i] : 0;
    if (i < NN) cnts[i] = 0;             // self-clean for next replay
    buf[0][t] = myc;
    __syncthreads();
    int cur = 0;
#pragma unroll
    for (int off = 1; off < 1024; off <<= 1) {
        int x = buf[cur][t];
        if (t >= off) x += buf[cur][t - off];
        buf[cur ^ 1][t] = x;
        cur ^= 1;
        __syncthreads();
    }
    int inc = buf[cur][t];
    if (i < NN) rowptr[i + 1] = inc;
    if (t == 1023) bsums[b] = inc;
}
__global__ void scan2_kernel(int* __restrict__ bsums, int nb) {
    __shared__ int buf[2][128];
    int t = threadIdx.x;
    int v = (t < nb) ? bsums[t] : 0;
    buf[0][t] = v;
    __syncthreads();
    int cur = 0;
#pragma unroll
    for (int off = 1; off < 128; off <<= 1) {
        int x = buf[cur][t];
        if (t >= off) x += buf[cur][t - off];
        buf[cur ^ 1][t] = x;
        cur ^= 1;
        __syncthreads();
    }
    if (t < nb) bsums[t] = buf[cur][t] - v;   // exclusive
}
__global__ void scan3_kernel(int* __restrict__ rowptr, const int* __restrict__ bsums,
                             int* __restrict__ cursor) {
    int b = blockIdx.x, t = threadIdx.x;
    int i = b * 1024 + t;
    if (i < NN) {
        int rp1 = rowptr[i + 1] + bsums[b];
        rowptr[i + 1] = rp1;
        if (i + 1 < NN) cursor[i + 1] = rp1;
    }
    if (i == 0) { rowptr[0] = 0; cursor[0] = 0; }
}
__global__ void fillcol_kernel(const int* __restrict__ dst, const int* __restrict__ src,
                               const float* __restrict__ eattr, int* __restrict__ cursor,
                               int* __restrict__ csrc, float* __restrict__ cea) {
    int e = blockIdx.x * blockDim.x + threadIdx.x;
    if (e >= EE) return;
    int pos = atomicAdd(&cursor[dst[e]], 1);
    csrc[pos] = src[e];
    cea[pos] = eattr[e];
}

// ---------------- tf32 MMA GEMM via cp.async: [xl|xr] = X @ WT^T + bias ----------------
// 512-thread CTA, tile 128(M) x 256(N): 16 warps as 2(M) x 8(N), warp tile 64x32.
// grid.y = 2 (y=0 -> xl, y=1 -> xr): A is read only 2x instead of 4x.
#define ROWPITCH 36
#define ASTAGEF (128 * ROWPITCH)
#define BSTAGEF (256 * ROWPITCH)
#define STAGEF  (ASTAGEF + BSTAGEF)

template <int K>
__global__ void __launch_bounds__(512, 1)
mma_lr_kernel(const float* __restrict__ X, const float* __restrict__ WT,
              const float* __restrict__ bl, const float* __restrict__ br,
              float* __restrict__ xl, float* __restrict__ xr, int n) {
    extern __shared__ float smf[];
    constexpr int NC = K / 32;

    int tid = threadIdx.x;               // 0..511
    int wid = tid >> 5, lane = tid & 31;
    int wm = wid & 1, wn = wid >> 1;     // 2(M) x 8(N)
    int tg = lane >> 2, tig = lane & 3;
    int row0 = blockIdx.x * 128;
    int nbase = blockIdx.y * 256;        // 0 -> Wl rows, 256 -> Wr rows
    uint32_t sbase = smem_u32(smf);

    auto issue_chunk = [&](int c) {
        int s = c & 1;
        uint32_t a_s = sbase + s * (STAGEF * 4);
        uint32_t b_s = a_s + ASTAGEF * 4;
        // A tile: 128 rows x 8 float4 = 1024 slots over 512 threads
#pragma unroll
        for (int j = 0; j < 2; j++) {
            int i = tid + j * 512;
            int r = i >> 3, q = i & 7;
            int row = row0 + r;
            bool ok = row < n;
            const float* ga = ok ? &X[(size_t)row * K + c * 32 + q * 4] : X;
            cp16(a_s + (uint32_t)(r * ROWPITCH + q * 4) * 4, ga, ok);
        }
        // B tile: 256 rows x 8 float4 = 2048 slots
#pragma unroll
        for (int j = 0; j < 4; j++) {
            int i = tid + j * 512;
            int r = i >> 3, q = i & 7;
            cp16(b_s + (uint32_t)(r * ROWPITCH + q * 4) * 4,
                 &WT[(size_t)(nbase + r) * K + c * 32 + q * 4], true);
        }
        asm volatile("cp.async.commit_group;");
    };

    float d[4][4][4];
#pragma unroll
    for (int i = 0; i < 4; i++)
#pragma unroll
        for (int j = 0; j < 4; j++)
#pragma unroll
            for (int q = 0; q < 4; q++) d[i][j][q] = 0.f;

    issue_chunk(0);
    if (NC > 1) issue_chunk(1);

#pragma unroll
    for (int c = 0; c < NC; c++) {
        if (c < NC - 1) asm volatile("cp.async.wait_group 1;");
        else            asm volatile("cp.async.wait_group 0;");
        __syncthreads();

        int s = c & 1;
        const uint32_t* As = (const uint32_t*)(smf + s * STAGEF);
        const uint32_t* Bs = As + ASTAGEF;
#pragma unroll
        for (int ks = 0; ks < 4; ks++) {
            uint32_t a[4][4], b[4][2];
#pragma unroll
            for (int mt = 0; mt < 4; mt++) {
                const uint32_t* p = As + (wm * 64 + mt * 16 + tg) * ROWPITCH + ks * 8 + tig;
                a[mt][0] = p[0];
                a[mt][1] = p[8 * ROWPITCH];
                a[mt][2] = p[4];
                a[mt][3] = p[8 * ROWPITCH + 4];
            }
#pragma unroll
            for (int nt = 0; nt < 4; nt++) {
                const uint32_t* p = Bs + (wn * 32 + nt * 8 + tg) * ROWPITCH + ks * 8 + tig;
                b[nt][0] = p[0];
                b[nt][1] = p[4];
            }
#pragma unroll
            for (int mt = 0; mt < 4; mt++)
#pragma unroll
                for (int nt = 0; nt < 4; nt++)
                    mma_tf32_16x8x8(d[mt][nt], a[mt], b[nt]);
        }

        if (c + 2 < NC) {
            __syncthreads();
            issue_chunk(c + 2);
        }
    }

    float* Y = (blockIdx.y == 0) ? xl : xr;
    const float* bias = (blockIdx.y == 0) ? bl : br;
#pragma unroll
    for (int mt = 0; mt < 4; mt++) {
        int r0 = row0 + wm * 64 + mt * 16 + tg;
#pragma unroll
        for (int nt = 0; nt < 4; nt++) {
            int col = wn * 32 + nt * 8 + 2 * tig;
            float2 bv = *(const float2*)&bias[col];
            if (r0 < n)
                *(float2*)&Y[(size_t)r0 * 256 + col] =
                    make_float2(d[mt][nt][0] + bv.x, d[mt][nt][1] + bv.y);
            if (r0 + 8 < n)
                *(float2*)&Y[(size_t)(r0 + 8) * 256 + col] =
                    make_float2(d[mt][nt][2] + bv.x, d[mt][nt][3] + bv.y);
        }
    }
}

// build WT[512,K] K-major from Wl/Wr [K,256]; pre-round to tf32
__global__ void build_wt_kernel(const float* __restrict__ Wl, const float* __restrict__ Wr,
                                float* __restrict__ WT, int K) {
    int idx = blockIdx.x * blockDim.x + threadIdx.x;
    if (idx >= 512 * K) return;
    int nrow = idx / K, k = idx - nrow * K;
    float v = (nrow < 256) ? Wl[k * 256 + nrow] : Wr[k * 256 + (nrow - 256)];
    WT[idx] = round_tf32(v);
}

// ---------------- encoder (output tf32-rounded; feeds only the layer-1 GEMM) ----------------
__global__ void enc_kernel(const float* __restrict__ x, const float* __restrict__ W,
                           const float* __restrict__ b, float* __restrict__ h0) {
    int idx = blockIdx.x * blockDim.x + threadIdx.x;
    if (idx >= NN * 64) return;
    int i = idx >> 6;
    int c = idx & 63;
    float acc = b[c];
#pragma unroll
    for (int k = 0; k < 8; k++) acc += x[i * 8 + k] * W[k * 64 + c];
    h0[idx] = round_tf32(fmaxf(acc, 0.f));
}

// ---------------- fused GAT aggregation: one warp per dst node, online softmax ----------------
template <bool ROUND>
__global__ void __launch_bounds__(256)
edge_fused_kernel(const float* __restrict__ xl, const float* __restrict__ xr,
                  const float* __restrict__ We, const float* __restrict__ att,
                  const int* __restrict__ rowptr,
                  const int* __restrict__ csrc, const float* __restrict__ cea,
                  const float* __restrict__ bias, float* __restrict__ h_out) {
    int d = blockIdx.x * 8 + (threadIdx.x >> 5);
    int lane = threadIdx.x & 31;
    if (d >= NN) return;
    int c0 = lane * 8;

    float4 xr0 = *(const float4*)&xr[d * 256 + c0];
    float4 xr1 = *(const float4*)&xr[d * 256 + c0 + 4];
    float4 we0 = *(const float4*)&We[c0];
    float4 we1 = *(const float4*)&We[c0 + 4];
    float4 at0 = *(const float4*)&att[c0];
    float4 at1 = *(const float4*)&att[c0 + 4];

    int beg = rowptr[d], end = rowptr[d + 1];
    float m = -INFINITY, den = 0.f;
    float acc[8] = {0.f, 0.f, 0.f, 0.f, 0.f, 0.f, 0.f, 0.f};

    int s_nxt = 0; float ea_nxt = 0.f;
    if (beg < end) { s_nxt = csrc[beg]; ea_nxt = cea[beg]; }

    for (int p = beg; p < end; p++) {
        int s = s_nxt; float ea = ea_nxt;
        if (p + 1 < end) { s_nxt = csrc[p + 1]; ea_nxt = cea[p + 1]; }

        float4 a0 = *(const float4*)&xl[s * 256 + c0];
        float4 a1 = *(const float4*)&xl[s * 256 + c0 + 4];

        float v0 = a0.x + xr0.x + ea * we0.x;
        float v1 = a0.y + xr0.y + ea * we0.y;
        float v2 = a0.z + xr0.z + ea * we0.z;
        float v3 = a0.w + xr0.w + ea * we0.w;
        float v4 = a1.x + xr1.x + ea * we1.x;
        float v5 = a1.y + xr1.y + ea * we1.y;
        float v6 = a1.z + xr1.z + ea * we1.z;
        float v7 = a1.w + xr1.w + ea * we1.w;
        v0 = (v0 > 0.f) ? v0 : 0.2f * v0;
        v1 = (v1 > 0.f) ? v1 : 0.2f * v1;
        v2 = (v2 > 0.f) ? v2 : 0.2f * v2;
        v3 = (v3 > 0.f) ? v3 : 0.2f * v3;
        v4 = (v4 > 0.f) ? v4 : 0.2f * v4;
        v5 = (v5 > 0.f) ? v5 : 0.2f * v5;
        v6 = (v6 > 0.f) ? v6 : 0.2f * v6;
        v7 = (v7 > 0.f) ? v7 : 0.2f * v7;

        float part = v0 * at0.x + v1 * at0.y + v2 * at0.z + v3 * at0.w
                   + v4 * at1.x + v5 * at1.y + v6 * at1.z + v7 * at1.w;
        part += __shfl_xor_sync(0xffffffffu, part, 1);
        part += __shfl_xor_sync(0xffffffffu, part, 2);
        part += __shfl_xor_sync(0xffffffffu, part, 4);
        float l = part;

        float m_new = fmaxf(m, l);
        float scale = __expf(m - m_new);
        float w = __expf(l - m_new);
        den = den * scale + w;
        acc[0] = acc[0] * scale + w * a0.x;
        acc[1] = acc[1] * scale + w * a0.y;
        acc[2] = acc[2] * scale + w * a0.z;
        acc[3] = acc[3] * scale + w * a0.w;
        acc[4] = acc[4] * scale + w * a1.x;
        acc[5] = acc[5] * scale + w * a1.y;
        acc[6] = acc[6] * scale + w * a1.z;
        acc[7] = acc[7] * scale + w * a1.w;
        m = m_new;
    }

    float inv = 1.f / (den + 1e-16f);
    float4 b0 = *(const float4*)&bias[c0];
    float4 b1 = *(const float4*)&bias[c0 + 4];
    float o[8];
    o[0] = fmaxf(acc[0] * inv + b0.x, 0.f);
    o[1] = fmaxf(acc[1] * inv + b0.y, 0.f);
    o[2] = fmaxf(acc[2] * inv + b0.z, 0.f);
    o[3] = fmaxf(acc[3] * inv + b0.w, 0.f);
    o[4] = fmaxf(acc[4] * inv + b1.x, 0.f);
    o[5] = fmaxf(acc[5] * inv + b1.y, 0.f);
    o[6] = fmaxf(acc[6] * inv + b1.z, 0.f);
    o[7] = fmaxf(acc[7] * inv + b1.w, 0.f);
    if (ROUND) {
#pragma unroll
        for (int i = 0; i < 8; i++) o[i] = round_tf32(o[i]);
    }
    *(float4*)&h_out[d * 256 + c0]     = make_float4(o[0], o[1], o[2], o[3]);
    *(float4*)&h_out[d * 256 + c0 + 4] = make_float4(o[4], o[5], o[6], o[7]);
}

// ---------------- mean pool (batch sorted) ----------------
__global__ void pool_kernel(const float* __restrict__ h, const int* __restrict__ batch,
                            float* __restrict__ sums, float* __restrict__ cnt) {
    int c = threadIdx.x;
    int n0 = blockIdx.x * 64;
    if (n0 >= NN) return;
    int cur = batch[n0];
    float acc = 0.f, fc = 0.f;
    for (int i = 0; i < 64; i++) {
        int node = n0 + i;
        if (node >= NN) break;
        int b = batch[node];
        if (b != cur) {
            atomicAdd(&sums[cur * 256 + c], acc);
            if (c == 0) atomicAdd(&cnt[cur], fc);
            acc = 0.f; fc = 0.f; cur = b;
        }
        acc += h[node * 256 + c];
        fc += 1.f;
    }
    atomicAdd(&sums[cur * 256 + c], acc);
    if (c == 0) atomicAdd(&cnt[cur], fc);
}

// ---------------- MLP head (also re-zeroes sums/cnt for next replay) ----------------
__global__ void head_kernel(float* __restrict__ sums, float* __restrict__ cnt,
                            const float* __restrict__ Wp1, const float* __restrict__ bp1,
                            const float* __restrict__ lng, const float* __restrict__ lnb,
                            const float* __restrict__ Wp2, const float* __restrict__ bp2,
                            const float* __restrict__ Wh, const float* __restrict__ bh,
                            float* __restrict__ out) {
    __shared__ float pool[256];
    __shared__ float pbuf[128];
    __shared__ float qbuf[64];
    __shared__ float redbuf[4];
    int g = blockIdx.x, t = threadIdx.x;
    float cn = fmaxf(cnt[g], 1.f);
    pool[t] = sums[g * 256 + t] / cn;
    pool[t + 128] = sums[g * 256 + 128 + t] / cn;
    sums[g * 256 + t] = 0.f;
    sums[g * 256 + 128 + t] = 0.f;
    if (t == 0) cnt[g] = 0.f;
    __syncthreads();

    float acc = bp1[t];
#pragma unroll 4
    for (int k = 0; k < 256; k++) acc += pool[k] * Wp1[k * 128 + t];

    float s = acc;
#pragma unroll
    for (int o = 16; o > 0; o >>= 1) s += __shfl_xor_sync(0xffffffffu, s, o);
    if ((t & 31) == 0) redbuf[t >> 5] = s;
    __syncthreads();
    float mu = (redbuf[0] + redbuf[1] + redbuf[2] + redbuf[3]) * (1.f / 128.f);
    __syncthreads();

    float dv = (acc - mu) * (acc - mu);
#pragma unroll
    for (int o = 16; o > 0; o >>= 1) dv += __shfl_xor_sync(0xffffffffu, dv, o);
    if ((t & 31) == 0) redbuf[t >> 5] = dv;
    __syncthreads();
    float var = (redbuf[0] + redbuf[1] + redbuf[2] + redbuf[3]) * (1.f / 128.f);

    float v = (acc - mu) * rsqrtf(var + 1e-5f) * lng[t] + lnb[t];
    pbuf[t] = fmaxf(v, 0.f);
    __syncthreads();

    if (t < 64) {
        float a = bp2[t];
#pragma unroll 4
        for (int k = 0; k < 128; k++) a += pbuf[k] * Wp2[k * 64 + t];
        qbuf[t] = fmaxf(a, 0.f);
    }
    __syncthreads();

    if (t < 32) {
        float a = qbuf[t] * Wh[t] + qbuf[t + 32] * Wh[t + 32];
#pragma unroll
        for (int o = 16; o > 0; o >>= 1) a += __shfl_xor_sync(0xffffffffu, a, o);
        if (t == 0) out[g] = a + bh[0];
    }
}

// ---------------- launch ----------------
static const int MMA_SMEM = 2 * STAGEF * 4;   // 2 stages x (A+B) floats

extern "C" void kernel_launch(void* const* d_in, const int* in_sizes, int n_in,
                              void* d_out, int out_size) {
    const float* x       = (const float*)d_in[0];
    const float* eattr   = (const float*)d_in[1];
    const int*   src     = (const int*)d_in[2];
    const int*   dst     = (const int*)d_in[3];
    const int*   batch   = (const int*)d_in[4];
    const float* W_enc   = (const float*)d_in[5];
    const float* b_enc   = (const float*)d_in[6];
    const float* g1_Wl   = (const float*)d_in[7];
    const float* g1_bl   = (const float*)d_in[8];
    const float* g1_Wr   = (const float*)d_in[9];
    const float* g1_br   = (const float*)d_in[10];
    const float* g1_We   = (const float*)d_in[11];
    const float* g1_att  = (const float*)d_in[12];
    const float* g1_bias = (const float*)d_in[13];
    const float* g2_Wl   = (const float*)d_in[14];
    const float* g2_bl   = (const float*)d_in[15];
    const float* g2_Wr   = (const float*)d_in[16];
    const float* g2_br   = (const float*)d_in[17];
    const float* g2_We   = (const float*)d_in[18];
    const float* g2_att  = (const float*)d_in[19];
    const float* g2_bias = (const float*)d_in[20];
    const float* W_p1    = (const float*)d_in[21];
    const float* b_p1    = (const float*)d_in[22];
    const float* ln_g    = (const float*)d_in[23];
    const float* ln_b    = (const float*)d_in[24];
    const float* W_p2    = (const float*)d_in[25];
    const float* b_p2    = (const float*)d_in[26];
    const float* W_head  = (const float*)d_in[27];
    const float* b_head  = (const float*)d_in[28];
    float* out = (float*)d_out;

    float *h0, *xl, *xr, *h1, *sums, *cnt, *wt, *cea;
    int *rowptr, *cnts, *cursor, *csrc, *bsums;
    cudaGetSymbolAddress((void**)&h0,     g_h0);
    cudaGetSymbolAddress((void**)&xl,     g_xl);
    cudaGetSymbolAddress((void**)&xr,     g_xr);
    cudaGetSymbolAddress((void**)&h1,     g_h1);
    cudaGetSymbolAddress((void**)&sums,   g_sums);
    cudaGetSymbolAddress((void**)&cnt,    g_cnt);
    cudaGetSymbolAddress((void**)&wt,     g_wt);
    cudaGetSymbolAddress((void**)&rowptr, g_rowptr);
    cudaGetSymbolAddress((void**)&cnts,   g_cnts);
    cudaGetSymbolAddress((void**)&cursor, g_cursor);
    cudaGetSymbolAddress((void**)&csrc,   g_csrc);
    cudaGetSymbolAddress((void**)&cea,    g_cea);
    cudaGetSymbolAddress((void**)&bsums,  g_bsums);

    cudaFuncSetAttribute(mma_lr_kernel<64>,  cudaFuncAttributeMaxDynamicSharedMemorySize, MMA_SMEM);
    cudaFuncSetAttribute(mma_lr_kernel<256>, cudaFuncAttributeMaxDynamicSharedMemorySize, MMA_SMEM);

    const int MT = (NN + 127) / 128;
    dim3 gemm_grid(MT, 2);
    const int NB_SCAN = (NN + 1023) / 1024;
    const int EW_GRID = (NN + 7) / 8;

    // harness adds 2 launches before these; ncu -s 5 -c 1 captures my index 3.
    enc_kernel<<<(NN * 64 + 255) / 256, 256>>>(x, W_enc, b_enc, h0);                   // 0
    build_wt_kernel<<<(512 * 64 + 255) / 256, 256>>>(g1_Wl, g1_Wr, wt, 64);            // 1
    hist_kernel<<<(EE + 255) / 256, 256>>>(dst, cnts);                                 // 2
    mma_lr_kernel<64><<<gemm_grid, 512, MMA_SMEM>>>(h0, wt, g1_bl, g1_br, xl, xr, NN); // 3 <- profiled
    scan1_kernel<<<NB_SCAN, 1024>>>(cnts, rowptr, bsums);                              // 4
    scan2_kernel<<<1, 128>>>(bsums, NB_SCAN);                                          // 5
    scan3_kernel<<<NB_SCAN, 1024>>>(rowptr, bsums, cursor);                            // 6
    fillcol_kernel<<<(EE + 255) / 256, 256>>>(dst, src, eattr, cursor, csrc, cea);     // 7

    edge_fused_kernel<true><<<EW_GRID, 256>>>(xl, xr, g1_We, g1_att,
                                              rowptr, csrc, cea, g1_bias, h1);

    build_wt_kernel<<<(512 * 256 + 255) / 256, 256>>>(g2_Wl, g2_Wr, wt, 256);
    mma_lr_kernel<256><<<gemm_grid, 512, MMA_SMEM>>>(h1, wt, g2_bl, g2_br, xl, xr, NN);
    edge_fused_kernel<false><<<EW_GRID, 256>>>(xl, xr, g2_We, g2_att,
                                               rowptr, csrc, cea, g2_bias, h1);

    pool_kernel<<<(NN + 63) / 64, 256>>>(h1, batch, sums, cnt);
    head_kernel<<<GG, 128>>>(sums, cnt, W_p1, b_p1, ln_g, ln_b, W_p2, b_p2, W_head, b_head, out);
}

// round 9
// speedup vs baseline: 1.0197x; 1.0197x over previous
#include <cuda_runtime.h>
#include <cuda_bf16.h>
#include <math.h>
#include <cstdint>

#define NN 100000
#define EE 400000
#define GG 64

// ---------------- scratch (device globals; no allocation allowed) ----------------
__device__ float g_h0[NN * 64];        // encoder output (tf32-rounded values)
__device__ float g_xl[NN * 256];       // source-side transform
__device__ float g_xr[NN * 256];       // target-side transform
__device__ float g_h1[NN * 256];       // layer output (tf32-rounded after layer 1)
__device__ float g_sums[GG * 256];     // pooled sums (zeroed by head_kernel after use)
__device__ float g_cnt[GG];            // node counts (zeroed by head_kernel after use)
__device__ float g_wt[512 * 256];      // fused transposed weights [512 n-rows, K] (tf32-rounded)
// CSR over dst (built once per launch; dst shared by both layers)
__device__ int   g_rowptr[NN + 1];
__device__ int   g_cnts[NN];           // histogram (self-cleared by scan1 each run)
__device__ int   g_cursor[NN];         // write cursors (seeded by scan3 each run)
__device__ int   g_csrc[EE];           // src id per CSR slot
__device__ float g_cea[EE];            // edge attr per CSR slot
__device__ int   g_bsums[128];

// ---------------- small utils ----------------
__device__ __forceinline__ uint32_t cvt_tf32(float x) {
    uint32_t r;
    asm("cvt.rna.tf32.f32 %0, %1;" : "=r"(r) : "f"(x));
    return r;
}
__device__ __forceinline__ float round_tf32(float x) {
    return __uint_as_float(cvt_tf32(x));
}
__device__ __forceinline__ uint32_t smem_u32(const void* p) {
    uint32_t a;
    asm("{ .reg .u64 t; cvta.to.shared.u64 t, %1; cvt.u32.u64 %0, t; }" : "=r"(a) : "l"(p));
    return a;
}
__device__ __forceinline__ void cp16(uint32_t saddr, const void* g, bool pred) {
    int sz = pred ? 16 : 0;
    asm volatile("cp.async.cg.shared.global [%0], [%1], 16, %2;"
                 :: "r"(saddr), "l"(g), "r"(sz));
}
__device__ __forceinline__ void mma_tf32_16x8x8(float* d, const uint32_t* a, const uint32_t* b) {
    asm volatile(
        "mma.sync.aligned.m16n8k8.row.col.f32.tf32.tf32.f32 "
        "{%0,%1,%2,%3}, {%4,%5,%6,%7}, {%8,%9}, {%0,%1,%2,%3};"
        : "+f"(d[0]), "+f"(d[1]), "+f"(d[2]), "+f"(d[3])
        : "r"(a[0]), "r"(a[1]), "r"(a[2]), "r"(a[3]), "r"(b[0]), "r"(b[1]));
}

// ---------------- CSR build over dst ----------------
__global__ void hist_kernel(const int* __restrict__ dst, int* __restrict__ cnts) {
    int e = blockIdx.x * blockDim.x + threadIdx.x;
    if (e < EE) atomicAdd(&cnts[dst[e]], 1);
}
__global__ void scan1_kernel(int* __restrict__ cnts, int* __restrict__ rowptr,
                             int* __restrict__ bsums) {
    __shared__ int buf[2][1024];
    int b = blockIdx.x, t = threadIdx.x;
    int i = b * 1024 + t;
    int myc = (i < NN) ? cnts[i] : 0;
    if (i < NN) cnts[i] = 0;             // self-clean for next replay
    buf[0][t] = myc;
    __syncthreads();
    int cur = 0;
#pragma unroll
    for (int off = 1; off < 1024; off <<= 1) {
        int x = buf[cur][t];
        if (t >= off) x += buf[cur][t - off];
        buf[cur ^ 1][t] = x;
        cur ^= 1;
        __syncthreads();
    }
    int inc = buf[cur][t];
    if (i < NN) rowptr[i + 1] = inc;
    if (t == 1023) bsums[b] = inc;
}
__global__ void scan2_kernel(int* __restrict__ bsums, int nb) {
    __shared__ int buf[2][128];
    int t = threadIdx.x;
    int v = (t < nb) ? bsums[t] : 0;
    buf[0][t] = v;
    __syncthreads();
    int cur = 0;
#pragma unroll
    for (int off = 1; off < 128; off <<= 1) {
        int x = buf[cur][t];
        if (t >= off) x += buf[cur][t - off];
        buf[cur ^ 1][t] = x;
        cur ^= 1;
        __syncthreads();
    }
    if (t < nb) bsums[t] = buf[cur][t] - v;   // exclusive
}
__global__ void scan3_kernel(int* __restrict__ rowptr, const int* __restrict__ bsums,
                             int* __restrict__ cursor) {
    int b = blockIdx.x, t = threadIdx.x;
    int i = b * 1024 + t;
    if (i < NN) {
        int rp1 = rowptr[i + 1] + bsums[b];
        rowptr[i + 1] = rp1;
        if (i + 1 < NN) cursor[i + 1] = rp1;
    }
    if (i == 0) { rowptr[0] = 0; cursor[0] = 0; }
}
__global__ void fillcol_kernel(const int* __restrict__ dst, const int* __restrict__ src,
                               const float* __restrict__ eattr, int* __restrict__ cursor,
                               int* __restrict__ csrc, float* __restrict__ cea) {
    int e = blockIdx.x * blockDim.x + threadIdx.x;
    if (e >= EE) return;
    int pos = atomicAdd(&cursor[dst[e]], 1);
    csrc[pos] = src[e];
    cea[pos] = eattr[e];
}

// ---------------- tf32 MMA GEMM via cp.async: [xl|xr] = X @ WT^T + bias ----------------
// Template on K and N-tile NT:
//   NT=128: 256 thr (8 warps 2x4), 2 CTAs/SM, grid.y=4  (best for K=64)
//   NT=256: 512 thr (16 warps 2x8), 1 CTA/SM, grid.y=2  (halves A traffic; best for K=256)
#define ROWPITCH 36

template <int K, int NT>
__global__ void __launch_bounds__(NT * 2, NT == 128 ? 2 : 1)
mma_lr_kernel(const float* __restrict__ X, const float* __restrict__ WT,
              const float* __restrict__ bl, const float* __restrict__ br,
              float* __restrict__ xl, float* __restrict__ xr, int n) {
    extern __shared__ float smf[];
    constexpr int NC = K / 32;
    constexpr int BLK = NT * 2;
    constexpr int ASTG = 128 * ROWPITCH;
    constexpr int BSTG = NT * ROWPITCH;
    constexpr int STG = ASTG + BSTG;

    int tid = threadIdx.x;
    int wid = tid >> 5, lane = tid & 31;
    int wm = wid & 1, wn = wid >> 1;         // 2(M) x NT/32(N)
    int tg = lane >> 2, tig = lane & 3;
    int row0 = blockIdx.x * 128;
    int nbase = blockIdx.y * NT;             // fused-row base in WT (0..511)
    uint32_t sbase = smem_u32(smf);

    auto issue_chunk = [&](int c) {
        int s = c & 1;
        uint32_t a_s = sbase + s * (STG * 4);
        uint32_t b_s = a_s + ASTG * 4;
#pragma unroll
        for (int j = 0; j < 1024 / BLK; j++) {   // A: 128 rows x 8 float4
            int i = tid + j * BLK;
            int r = i >> 3, q = i & 7;
            int row = row0 + r;
            bool ok = row < n;
            const float* ga = ok ? &X[(size_t)row * K + c * 32 + q * 4] : X;
            cp16(a_s + (uint32_t)(r * ROWPITCH + q * 4) * 4, ga, ok);
        }
#pragma unroll
        for (int j = 0; j < NT * 8 / BLK; j++) { // B: NT rows x 8 float4
            int i = tid + j * BLK;
            int r = i >> 3, q = i & 7;
            cp16(b_s + (uint32_t)(r * ROWPITCH + q * 4) * 4,
                 &WT[(size_t)(nbase + r) * K + c * 32 + q * 4], true);
        }
        asm volatile("cp.async.commit_group;");
    };

    float d[4][4][4];
#pragma unroll
    for (int i = 0; i < 4; i++)
#pragma unroll
        for (int j = 0; j < 4; j++)
#pragma unroll
            for (int q = 0; q < 4; q++) d[i][j][q] = 0.f;

    issue_chunk(0);
    if (NC > 1) issue_chunk(1);

#pragma unroll
    for (int c = 0; c < NC; c++) {
        if (c < NC - 1) asm volatile("cp.async.wait_group 1;");
        else            asm volatile("cp.async.wait_group 0;");
        __syncthreads();

        int s = c & 1;
        const uint32_t* As = (const uint32_t*)(smf + s * STG);
        const uint32_t* Bs = As + ASTG;
#pragma unroll
        for (int ks = 0; ks < 4; ks++) {
            uint32_t a[4][4], b[4][2];
#pragma unroll
            for (int mt = 0; mt < 4; mt++) {
                const uint32_t* p = As + (wm * 64 + mt * 16 + tg) * ROWPITCH + ks * 8 + tig;
                a[mt][0] = p[0];
                a[mt][1] = p[8 * ROWPITCH];
                a[mt][2] = p[4];
                a[mt][3] = p[8 * ROWPITCH + 4];
            }
#pragma unroll
            for (int nt = 0; nt < 4; nt++) {
                const uint32_t* p = Bs + (wn * 32 + nt * 8 + tg) * ROWPITCH + ks * 8 + tig;
                b[nt][0] = p[0];
                b[nt][1] = p[4];
            }
#pragma unroll
            for (int mt = 0; mt < 4; mt++)
#pragma unroll
                for (int nt = 0; nt < 4; nt++)
                    mma_tf32_16x8x8(d[mt][nt], a[mt], b[nt]);
        }

        if (c + 2 < NC) {
            __syncthreads();
            issue_chunk(c + 2);
        }
    }

    // epilogue: map fused n-range back to (xl|xr, col)
    bool is_l = (nbase < 256);
    float* Y = is_l ? xl : xr;
    const float* bias = is_l ? bl : br;
    int colb = nbase & 255;
#pragma unroll
    for (int mt = 0; mt < 4; mt++) {
        int r0 = row0 + wm * 64 + mt * 16 + tg;
#pragma unroll
        for (int nt = 0; nt < 4; nt++) {
            int col = colb + wn * 32 + nt * 8 + 2 * tig;
            float2 bv = *(const float2*)&bias[col];
            if (r0 < n)
                *(float2*)&Y[(size_t)r0 * 256 + col] =
                    make_float2(d[mt][nt][0] + bv.x, d[mt][nt][1] + bv.y);
            if (r0 + 8 < n)
                *(float2*)&Y[(size_t)(r0 + 8) * 256 + col] =
                    make_float2(d[mt][nt][2] + bv.x, d[mt][nt][3] + bv.y);
        }
    }
}

// build WT[512,K] K-major from Wl/Wr [K,256]; pre-round to tf32
__global__ void build_wt_kernel(const float* __restrict__ Wl, const float* __restrict__ Wr,
                                float* __restrict__ WT, int K) {
    int idx = blockIdx.x * blockDim.x + threadIdx.x;
    if (idx >= 512 * K) return;
    int nrow = idx / K, k = idx - nrow * K;
    float v = (nrow < 256) ? Wl[k * 256 + nrow] : Wr[k * 256 + (nrow - 256)];
    WT[idx] = round_tf32(v);
}

// ---------------- encoder (output tf32-rounded; feeds only the layer-1 GEMM) ----------------
__global__ void enc_kernel(const float* __restrict__ x, const float* __restrict__ W,
                           const float* __restrict__ b, float* __restrict__ h0) {
    int idx = blockIdx.x * blockDim.x + threadIdx.x;
    if (idx >= NN * 64) return;
    int i = idx >> 6;
    int c = idx & 63;
    float acc = b[c];
#pragma unroll
    for (int k = 0; k < 8; k++) acc += x[i * 8 + k] * W[k * 64 + c];
    h0[idx] = round_tf32(fmaxf(acc, 0.f));
}

// ---------------- fused GAT aggregation: one warp per dst node, online softmax ----------------
template <bool ROUND>
__global__ void __launch_bounds__(256)
edge_fused_kernel(const float* __restrict__ xl, const float* __restrict__ xr,
                  const float* __restrict__ We, const float* __restrict__ att,
                  const int* __restrict__ rowptr,
                  const int* __restrict__ csrc, const float* __restrict__ cea,
                  const float* __restrict__ bias, float* __restrict__ h_out) {
    int d = blockIdx.x * 8 + (threadIdx.x >> 5);
    int lane = threadIdx.x & 31;
    if (d >= NN) return;
    int c0 = lane * 8;

    float4 xr0 = *(const float4*)&xr[d * 256 + c0];
    float4 xr1 = *(const float4*)&xr[d * 256 + c0 + 4];
    float4 we0 = *(const float4*)&We[c0];
    float4 we1 = *(const float4*)&We[c0 + 4];
    float4 at0 = *(const float4*)&att[c0];
    float4 at1 = *(const float4*)&att[c0 + 4];

    int beg = rowptr[d], end = rowptr[d + 1];
    float m = -INFINITY, den = 0.f;
    float acc[8] = {0.f, 0.f, 0.f, 0.f, 0.f, 0.f, 0.f, 0.f};

    int s_nxt = 0; float ea_nxt = 0.f;
    if (beg < end) { s_nxt = csrc[beg]; ea_nxt = cea[beg]; }

    for (int p = beg; p < end; p++) {
        int s = s_nxt; float ea = ea_nxt;
        if (p + 1 < end) { s_nxt = csrc[p + 1]; ea_nxt = cea[p + 1]; }

        float4 a0 = *(const float4*)&xl[s * 256 + c0];
        float4 a1 = *(const float4*)&xl[s * 256 + c0 + 4];

        float v0 = a0.x + xr0.x + ea * we0.x;
        float v1 = a0.y + xr0.y + ea * we0.y;
        float v2 = a0.z + xr0.z + ea * we0.z;
        float v3 = a0.w + xr0.w + ea * we0.w;
        float v4 = a1.x + xr1.x + ea * we1.x;
        float v5 = a1.y + xr1.y + ea * we1.y;
        float v6 = a1.z + xr1.z + ea * we1.z;
        float v7 = a1.w + xr1.w + ea * we1.w;
        v0 = (v0 > 0.f) ? v0 : 0.2f * v0;
        v1 = (v1 > 0.f) ? v1 : 0.2f * v1;
        v2 = (v2 > 0.f) ? v2 : 0.2f * v2;
        v3 = (v3 > 0.f) ? v3 : 0.2f * v3;
        v4 = (v4 > 0.f) ? v4 : 0.2f * v4;
        v5 = (v5 > 0.f) ? v5 : 0.2f * v5;
        v6 = (v6 > 0.f) ? v6 : 0.2f * v6;
        v7 = (v7 > 0.f) ? v7 : 0.2f * v7;

        float part = v0 * at0.x + v1 * at0.y + v2 * at0.z + v3 * at0.w
                   + v4 * at1.x + v5 * at1.y + v6 * at1.z + v7 * at1.w;
        part += __shfl_xor_sync(0xffffffffu, part, 1);
        part += __shfl_xor_sync(0xffffffffu, part, 2);
        part += __shfl_xor_sync(0xffffffffu, part, 4);
        float l = part;

        float m_new = fmaxf(m, l);
        float scale = __expf(m - m_new);
        float w = __expf(l - m_new);
        den = den * scale + w;
        acc[0] = acc[0] * scale + w * a0.x;
        acc[1] = acc[1] * scale + w * a0.y;
        acc[2] = acc[2] * scale + w * a0.z;
        acc[3] = acc[3] * scale + w * a0.w;
        acc[4] = acc[4] * scale + w * a1.x;
        acc[5] = acc[5] * scale + w * a1.y;
        acc[6] = acc[6] * scale + w * a1.z;
        acc[7] = acc[7] * scale + w * a1.w;
        m = m_new;
    }

    float inv = 1.f / (den + 1e-16f);
    float4 b0 = *(const float4*)&bias[c0];
    float4 b1 = *(const float4*)&bias[c0 + 4];
    float o[8];
    o[0] = fmaxf(acc[0] * inv + b0.x, 0.f);
    o[1] = fmaxf(acc[1] * inv + b0.y, 0.f);
    o[2] = fmaxf(acc[2] * inv + b0.z, 0.f);
    o[3] = fmaxf(acc[3] * inv + b0.w, 0.f);
    o[4] = fmaxf(acc[4] * inv + b1.x, 0.f);
    o[5] = fmaxf(acc[5] * inv + b1.y, 0.f);
    o[6] = fmaxf(acc[6] * inv + b1.z, 0.f);
    o[7] = fmaxf(acc[7] * inv + b1.w, 0.f);
    if (ROUND) {
#pragma unroll
        for (int i = 0; i < 8; i++) o[i] = round_tf32(o[i]);
    }
    *(float4*)&h_out[d * 256 + c0]     = make_float4(o[0], o[1], o[2], o[3]);
    *(float4*)&h_out[d * 256 + c0 + 4] = make_float4(o[4], o[5], o[6], o[7]);
}

// ---------------- mean pool (batch sorted) ----------------
__global__ void pool_kernel(const float* __restrict__ h, const int* __restrict__ batch,
                            float* __restrict__ sums, float* __restrict__ cnt) {
    int c = threadIdx.x;
    int n0 = blockIdx.x * 64;
    if (n0 >= NN) return;
    int cur = batch[n0];
    float acc = 0.f, fc = 0.f;
    for (int i = 0; i < 64; i++) {
        int node = n0 + i;
        if (node >= NN) break;
        int b = batch[node];
        if (b != cur) {
            atomicAdd(&sums[cur * 256 + c], acc);
            if (c == 0) atomicAdd(&cnt[cur], fc);
            acc = 0.f; fc = 0.f; cur = b;
        }
        acc += h[node * 256 + c];
        fc += 1.f;
    }
    atomicAdd(&sums[cur * 256 + c], acc);
    if (c == 0) atomicAdd(&cnt[cur], fc);
}

// ---------------- MLP head (also re-zeroes sums/cnt for next replay) ----------------
__global__ void head_kernel(float* __restrict__ sums, float* __restrict__ cnt,
                            const float* __restrict__ Wp1, const float* __restrict__ bp1,
                            const float* __restrict__ lng, const float* __restrict__ lnb,
                            const float* __restrict__ Wp2, const float* __restrict__ bp2,
                            const float* __restrict__ Wh, const float* __restrict__ bh,
                            float* __restrict__ out) {
    __shared__ float pool[256];
    __shared__ float pbuf[128];
    __shared__ float qbuf[64];
    __shared__ float redbuf[4];
    int g = blockIdx.x, t = threadIdx.x;
    float cn = fmaxf(cnt[g], 1.f);
    pool[t] = sums[g * 256 + t] / cn;
    pool[t + 128] = sums[g * 256 + 128 + t] / cn;
    sums[g * 256 + t] = 0.f;
    sums[g * 256 + 128 + t] = 0.f;
    if (t == 0) cnt[g] = 0.f;
    __syncthreads();

    float acc = bp1[t];
#pragma unroll 4
    for (int k = 0; k < 256; k++) acc += pool[k] * Wp1[k * 128 + t];

    float s = acc;
#pragma unroll
    for (int o = 16; o > 0; o >>= 1) s += __shfl_xor_sync(0xffffffffu, s, o);
    if ((t & 31) == 0) redbuf[t >> 5] = s;
    __syncthreads();
    float mu = (redbuf[0] + redbuf[1] + redbuf[2] + redbuf[3]) * (1.f / 128.f);
    __syncthreads();

    float dv = (acc - mu) * (acc - mu);
#pragma unroll
    for (int o = 16; o > 0; o >>= 1) dv += __shfl_xor_sync(0xffffffffu, dv, o);
    if ((t & 31) == 0) redbuf[t >> 5] = dv;
    __syncthreads();
    float var = (redbuf[0] + redbuf[1] + redbuf[2] + redbuf[3]) * (1.f / 128.f);

    float v = (acc - mu) * rsqrtf(var + 1e-5f) * lng[t] + lnb[t];
    pbuf[t] = fmaxf(v, 0.f);
    __syncthreads();

    if (t < 64) {
        float a = bp2[t];
#pragma unroll 4
        for (int k = 0; k < 128; k++) a += pbuf[k] * Wp2[k * 64 + t];
        qbuf[t] = fmaxf(a, 0.f);
    }
    __syncthreads();

    if (t < 32) {
        float a = qbuf[t] * Wh[t] + qbuf[t + 32] * Wh[t + 32];
#pragma unroll
        for (int o = 16; o > 0; o >>= 1) a += __shfl_xor_sync(0xffffffffu, a, o);
        if (t == 0) out[g] = a + bh[0];
    }
}

// ---------------- launch ----------------
static const int SMEM_NT128 = 2 * (128 + 128) * ROWPITCH * 4;   // 73728 B
static const int SMEM_NT256 = 2 * (128 + 256) * ROWPITCH * 4;   // 110592 B

extern "C" void kernel_launch(void* const* d_in, const int* in_sizes, int n_in,
                              void* d_out, int out_size) {
    const float* x       = (const float*)d_in[0];
    const float* eattr   = (const float*)d_in[1];
    const int*   src     = (const int*)d_in[2];
    const int*   dst     = (const int*)d_in[3];
    const int*   batch   = (const int*)d_in[4];
    const float* W_enc   = (const float*)d_in[5];
    const float* b_enc   = (const float*)d_in[6];
    const float* g1_Wl   = (const float*)d_in[7];
    const float* g1_bl   = (const float*)d_in[8];
    const float* g1_Wr   = (const float*)d_in[9];
    const float* g1_br   = (const float*)d_in[10];
    const float* g1_We   = (const float*)d_in[11];
    const float* g1_att  = (const float*)d_in[12];
    const float* g1_bias = (const float*)d_in[13];
    const float* g2_Wl   = (const float*)d_in[14];
    const float* g2_bl   = (const float*)d_in[15];
    const float* g2_Wr   = (const float*)d_in[16];
    const float* g2_br   = (const float*)d_in[17];
    const float* g2_We   = (const float*)d_in[18];
    const float* g2_att  = (const float*)d_in[19];
    const float* g2_bias = (const float*)d_in[20];
    const float* W_p1    = (const float*)d_in[21];
    const float* b_p1    = (const float*)d_in[22];
    const float* ln_g    = (const float*)d_in[23];
    const float* ln_b    = (const float*)d_in[24];
    const float* W_p2    = (const float*)d_in[25];
    const float* b_p2    = (const float*)d_in[26];
    const float* W_head  = (const float*)d_in[27];
    const float* b_head  = (const float*)d_in[28];
    float* out = (float*)d_out;

    float *h0, *xl, *xr, *h1, *sums, *cnt, *wt, *cea;
    int *rowptr, *cnts, *cursor, *csrc, *bsums;
    cudaGetSymbolAddress((void**)&h0,     g_h0);
    cudaGetSymbolAddress((void**)&xl,     g_xl);
    cudaGetSymbolAddress((void**)&xr,     g_xr);
    cudaGetSymbolAddress((void**)&h1,     g_h1);
    cudaGetSymbolAddress((void**)&sums,   g_sums);
    cudaGetSymbolAddress((void**)&cnt,    g_cnt);
    cudaGetSymbolAddress((void**)&wt,     g_wt);
    cudaGetSymbolAddress((void**)&rowptr, g_rowptr);
    cudaGetSymbolAddress((void**)&cnts,   g_cnts);
    cudaGetSymbolAddress((void**)&cursor, g_cursor);
    cudaGetSymbolAddress((void**)&csrc,   g_csrc);
    cudaGetSymbolAddress((void**)&cea,    g_cea);
    cudaGetSymbolAddress((void**)&bsums,  g_bsums);

    cudaFuncSetAttribute((const void*)mma_lr_kernel<64, 128>,
                         cudaFuncAttributeMaxDynamicSharedMemorySize, SMEM_NT128);
    cudaFuncSetAttribute((const void*)mma_lr_kernel<256, 256>,
                         cudaFuncAttributeMaxDynamicSharedMemorySize, SMEM_NT256);

    const int MT = (NN + 127) / 128;
    const int NB_SCAN = (NN + 1023) / 1024;
    const int EW_GRID = (NN + 7) / 8;

    // harness adds 2 launches before these; ncu -s 5 -c 1 captures my index 3.
    enc_kernel<<<(NN * 64 + 255) / 256, 256>>>(x, W_enc, b_enc, h0);                   // 0
    build_wt_kernel<<<(512 * 64 + 255) / 256, 256>>>(g1_Wl, g1_Wr, wt, 64);            // 1
    hist_kernel<<<(EE + 255) / 256, 256>>>(dst, cnts);                                 // 2
    mma_lr_kernel<64, 128><<<dim3(MT, 4), 256, SMEM_NT128>>>(h0, wt, g1_bl, g1_br,
                                                             xl, xr, NN);              // 3 <- profiled
    scan1_kernel<<<NB_SCAN, 1024>>>(cnts, rowptr, bsums);                              // 4
    scan2_kernel<<<1, 128>>>(bsums, NB_SCAN);                                          // 5
    scan3_kernel<<<NB_SCAN, 1024>>>(rowptr, bsums, cursor);                            // 6
    fillcol_kernel<<<(EE + 255) / 256, 256>>>(dst, src, eattr, cursor, csrc, cea);     // 7

    edge_fused_kernel<true><<<EW_GRID, 256>>>(xl, xr, g1_We, g1_att,
                                              rowptr, csrc, cea, g1_bias, h1);

    build_wt_kernel<<<(512 * 256 + 255) / 256, 256>>>(g2_Wl, g2_Wr, wt, 256);
    mma_lr_kernel<256, 256><<<dim3(MT, 2), 512, SMEM_NT256>>>(h1, wt, g2_bl, g2_br,
                                                              xl, xr, NN);
    edge_fused_kernel<false><<<EW_GRID, 256>>>(xl, xr, g2_We, g2_att,
                                               rowptr, csrc, cea, g2_bias, h1);

    pool_kernel<<<(NN + 63) / 64, 256>>>(h1, batch, sums, cnt);
    head_kernel<<<GG, 128>>>(sums, cnt, W_p1, b_p1, ln_g, ln_b, W_p2, b_p2, W_head, b_head, out);
}

// round 10
// speedup vs baseline: 1.0445x; 1.0244x over previous
#include <cuda_runtime.h>
#include <cuda_bf16.h>
#include <math.h>
#include <cstdint>

#define NN 100000
#define EE 400000
#define GG 64

// ---------------- scratch (device globals; no allocation allowed) ----------------
__device__ float g_h0[NN * 64];        // encoder output (tf32-rounded values)
__device__ float g_xl[NN * 256];       // source-side transform
__device__ float g_xr[NN * 256];       // target-side transform
__device__ float g_h1[NN * 256];       // layer output (tf32-rounded after layer 1)
__device__ float g_sums[GG * 256];     // pooled sums (zeroed by head_kernel after use)
__device__ float g_cnt[GG];            // node counts (zeroed by head_kernel after use)
__device__ float g_wt[512 * 256];      // fused transposed weights [512 n-rows, K] (tf32-rounded)
// CSR over dst (built once per launch; dst shared by both layers)
__device__ int   g_rowptr[NN + 1];
__device__ int   g_cnts[NN];           // histogram (self-cleared by scan1 each run)
__device__ int   g_cursor[NN];         // write cursors (seeded by scan3 each run)
__device__ int   g_csrc[EE];           // src id per CSR slot
__device__ float g_cea[EE];            // edge attr per CSR slot
__device__ int   g_bsums[128];

// ---------------- small utils ----------------
__device__ __forceinline__ uint32_t cvt_tf32(float x) {
    uint32_t r;
    asm("cvt.rna.tf32.f32 %0, %1;" : "=r"(r) : "f"(x));
    return r;
}
__device__ __forceinline__ float round_tf32(float x) {
    return __uint_as_float(cvt_tf32(x));
}
__device__ __forceinline__ uint32_t smem_u32(const void* p) {
    uint32_t a;
    asm("{ .reg .u64 t; cvta.to.shared.u64 t, %1; cvt.u32.u64 %0, t; }" : "=r"(a) : "l"(p));
    return a;
}
__device__ __forceinline__ void cp16(uint32_t saddr, const void* g, bool pred) {
    int sz = pred ? 16 : 0;
    asm volatile("cp.async.cg.shared.global [%0], [%1], 16, %2;"
                 :: "r"(saddr), "l"(g), "r"(sz));
}
__device__ __forceinline__ void mma_tf32_16x8x8(float* d, const uint32_t* a, const uint32_t* b) {
    asm volatile(
        "mma.sync.aligned.m16n8k8.row.col.f32.tf32.tf32.f32 "
        "{%0,%1,%2,%3}, {%4,%5,%6,%7}, {%8,%9}, {%0,%1,%2,%3};"
        : "+f"(d[0]), "+f"(d[1]), "+f"(d[2]), "+f"(d[3])
        : "r"(a[0]), "r"(a[1]), "r"(a[2]), "r"(a[3]), "r"(b[0]), "r"(b[1]));
}

// ---------------- CSR build over dst ----------------
__global__ void hist_kernel(const int* __restrict__ dst, int* __restrict__ cnts) {
    int e = blockIdx.x * blockDim.x + threadIdx.x;
    if (e < EE) atomicAdd(&cnts[dst[e]], 1);
}
__global__ void scan1_kernel(int* __restrict__ cnts, int* __restrict__ rowptr,
                             int* __restrict__ bsums) {
    __shared__ int buf[2][1024];
    int b = blockIdx.x, t = threadIdx.x;
    int i = b * 1024 + t;
    int myc = (i < NN) ? cnts[i] : 0;
    if (i < NN) cnts[i] = 0;             // self-clean for next replay
    buf[0][t] = myc;
    __syncthreads();
    int cur = 0;
#pragma unroll
    for (int off = 1; off < 1024; off <<= 1) {
        int x = buf[cur][t];
        if (t >= off) x += buf[cur][t - off];
        buf[cur ^ 1][t] = x;
        cur ^= 1;
        __syncthreads();
    }
    int inc = buf[cur][t];
    if (i < NN) rowptr[i + 1] = inc;
    if (t == 1023) bsums[b] = inc;
}
__global__ void scan2_kernel(int* __restrict__ bsums, int nb) {
    __shared__ int buf[2][128];
    int t = threadIdx.x;
    int v = (t < nb) ? bsums[t] : 0;
    buf[0][t] = v;
    __syncthreads();
    int cur = 0;
#pragma unroll
    for (int off = 1; off < 128; off <<= 1) {
        int x = buf[cur][t];
        if (t >= off) x += buf[cur][t - off];
        buf[cur ^ 1][t] = x;
        cur ^= 1;
        __syncthreads();
    }
    if (t < nb) bsums[t] = buf[cur][t] - v;   // exclusive
}
__global__ void scan3_kernel(int* __restrict__ rowptr, const int* __restrict__ bsums,
                             int* __restrict__ cursor) {
    int b = blockIdx.x, t = threadIdx.x;
    int i = b * 1024 + t;
    if (i < NN) {
        int rp1 = rowptr[i + 1] + bsums[b];
        rowptr[i + 1] = rp1;
        if (i + 1 < NN) cursor[i + 1] = rp1;
    }
    if (i == 0) { rowptr[0] = 0; cursor[0] = 0; }
}
__global__ void fillcol_kernel(const int* __restrict__ dst, const int* __restrict__ src,
                               const float* __restrict__ eattr, int* __restrict__ cursor,
                               int* __restrict__ csrc, float* __restrict__ cea) {
    int e = blockIdx.x * blockDim.x + threadIdx.x;
    if (e >= EE) return;
    int pos = atomicAdd(&cursor[dst[e]], 1);
    csrc[pos] = src[e];
    cea[pos] = eattr[e];
}

// ---------------- tf32 MMA GEMM via cp.async: [xl|xr] = X @ WT^T + bias ----------------
// Round-7 proven shape: 128x128 CTA tile, 256 thr (8 warps 2x4), 2 CTAs/SM, grid.y=4.
// STAGES: 2 for K=64 (NC=2), 3 for K=256 (NC=8) to cover the DRAM load tail.
#define ROWPITCH 36
#define STAGEF (256 * ROWPITCH)          // A(128 rows) + B(128 rows) per stage

template <int K>
__global__ void __launch_bounds__(256, 2)
mma_lr_kernel(const float* __restrict__ X, const float* __restrict__ WT,
              const float* __restrict__ bl, const float* __restrict__ br,
              float* __restrict__ xl, float* __restrict__ xr, int n) {
    extern __shared__ float smf[];
    constexpr int NC = K / 32;
    constexpr int STAGES = (NC >= 3) ? 3 : 2;

    int tid = threadIdx.x;
    int wid = tid >> 5, lane = tid & 31;
    int wm = wid & 1, wn = wid >> 1;
    int tg = lane >> 2, tig = lane & 3;
    int row0 = blockIdx.x * 128;
    int nbase = blockIdx.y * 128;        // fused-row base in WT (0..511)
    uint32_t sbase = smem_u32(smf);

    auto issue_chunk = [&](int c) {
        int s = c % STAGES;
        uint32_t a_s = sbase + s * (STAGEF * 4);
        uint32_t b_s = a_s + 128 * ROWPITCH * 4;
#pragma unroll
        for (int j = 0; j < 4; j++) {
            int i = tid + j * 256;
            int r = i >> 3, q = i & 7;
            int row = row0 + r;
            bool ok = row < n;
            const float* ga = ok ? &X[(size_t)row * K + c * 32 + q * 4] : X;
            cp16(a_s + (uint32_t)(r * ROWPITCH + q * 4) * 4, ga, ok);
            cp16(b_s + (uint32_t)(r * ROWPITCH + q * 4) * 4,
                 &WT[(size_t)(nbase + r) * K + c * 32 + q * 4], true);
        }
        asm volatile("cp.async.commit_group;");
    };

    float d[4][4][4];
#pragma unroll
    for (int i = 0; i < 4; i++)
#pragma unroll
        for (int j = 0; j < 4; j++)
#pragma unroll
            for (int q = 0; q < 4; q++) d[i][j][q] = 0.f;

#pragma unroll
    for (int c = 0; c < STAGES && c < NC; c++) issue_chunk(c);

#pragma unroll
    for (int c = 0; c < NC; c++) {
        if (c + STAGES <= NC)      asm volatile("cp.async.wait_group %0;" :: "n"(STAGES - 1));
        else if (c + 2 == NC)      asm volatile("cp.async.wait_group 1;");
        else if (c + 1 == NC)      asm volatile("cp.async.wait_group 0;");
        __syncthreads();

        int s = c % STAGES;
        const uint32_t* As = (const uint32_t*)(smf + s * STAGEF);
        const uint32_t* Bs = As + 128 * ROWPITCH;
#pragma unroll
        for (int ks = 0; ks < 4; ks++) {
            uint32_t a[4][4], b[4][2];
#pragma unroll
            for (int mt = 0; mt < 4; mt++) {
                const uint32_t* p = As + (wm * 64 + mt * 16 + tg) * ROWPITCH + ks * 8 + tig;
                a[mt][0] = p[0];
                a[mt][1] = p[8 * ROWPITCH];
                a[mt][2] = p[4];
                a[mt][3] = p[8 * ROWPITCH + 4];
            }
#pragma unroll
            for (int nt = 0; nt < 4; nt++) {
                const uint32_t* p = Bs + (wn * 32 + nt * 8 + tg) * ROWPITCH + ks * 8 + tig;
                b[nt][0] = p[0];
                b[nt][1] = p[4];
            }
#pragma unroll
            for (int mt = 0; mt < 4; mt++)
#pragma unroll
                for (int nt = 0; nt < 4; nt++)
                    mma_tf32_16x8x8(d[mt][nt], a[mt], b[nt]);
        }

        if (c + STAGES < NC) {
            __syncthreads();
            issue_chunk(c + STAGES);
        }
    }

    // epilogue: blockIdx.y 0,1 -> xl cols 0/128 ; 2,3 -> xr cols 0/128
    bool is_l = (nbase < 256);
    float* Y = is_l ? xl : xr;
    const float* bias = is_l ? bl : br;
    int colb = nbase & 255;
#pragma unroll
    for (int mt = 0; mt < 4; mt++) {
        int r0 = row0 + wm * 64 + mt * 16 + tg;
#pragma unroll
        for (int nt = 0; nt < 4; nt++) {
            int col = colb + wn * 32 + nt * 8 + 2 * tig;
            float2 bv = *(const float2*)&bias[col];
            if (r0 < n)
                *(float2*)&Y[(size_t)r0 * 256 + col] =
                    make_float2(d[mt][nt][0] + bv.x, d[mt][nt][1] + bv.y);
            if (r0 + 8 < n)
                *(float2*)&Y[(size_t)(r0 + 8) * 256 + col] =
                    make_float2(d[mt][nt][2] + bv.x, d[mt][nt][3] + bv.y);
        }
    }
}

// build WT[512,K] K-major from Wl/Wr [K,256]; pre-round to tf32
__global__ void build_wt_kernel(const float* __restrict__ Wl, const float* __restrict__ Wr,
                                float* __restrict__ WT, int K) {
    int idx = blockIdx.x * blockDim.x + threadIdx.x;
    if (idx >= 512 * K) return;
    int nrow = idx / K, k = idx - nrow * K;
    float v = (nrow < 256) ? Wl[k * 256 + nrow] : Wr[k * 256 + (nrow - 256)];
    WT[idx] = round_tf32(v);
}

// ---------------- encoder (output tf32-rounded; feeds only the layer-1 GEMM) ----------------
__global__ void enc_kernel(const float* __restrict__ x, const float* __restrict__ W,
                           const float* __restrict__ b, float* __restrict__ h0) {
    int idx = blockIdx.x * blockDim.x + threadIdx.x;
    if (idx >= NN * 64) return;
    int i = idx >> 6;
    int c = idx & 63;
    float acc = b[c];
#pragma unroll
    for (int k = 0; k < 8; k++) acc += x[i * 8 + k] * W[k * 64 + c];
    h0[idx] = round_tf32(fmaxf(acc, 0.f));
}

// ---------------- fused GAT aggregation: one warp per dst node, online softmax ----------------
template <bool ROUND>
__global__ void __launch_bounds__(256)
edge_fused_kernel(const float* __restrict__ xl, const float* __restrict__ xr,
                  const float* __restrict__ We, const float* __restrict__ att,
                  const int* __restrict__ rowptr,
                  const int* __restrict__ csrc, const float* __restrict__ cea,
                  const float* __restrict__ bias, float* __restrict__ h_out) {
    int d = blockIdx.x * 8 + (threadIdx.x >> 5);
    int lane = threadIdx.x & 31;
    if (d >= NN) return;
    int c0 = lane * 8;

    float4 xr0 = *(const float4*)&xr[d * 256 + c0];
    float4 xr1 = *(const float4*)&xr[d * 256 + c0 + 4];
    float4 we0 = *(const float4*)&We[c0];
    float4 we1 = *(const float4*)&We[c0 + 4];
    float4 at0 = *(const float4*)&att[c0];
    float4 at1 = *(const float4*)&att[c0 + 4];

    int beg = rowptr[d], end = rowptr[d + 1];
    float m = -INFINITY, den = 0.f;
    float acc[8] = {0.f, 0.f, 0.f, 0.f, 0.f, 0.f, 0.f, 0.f};

    int s_nxt = 0; float ea_nxt = 0.f;
    if (beg < end) { s_nxt = csrc[beg]; ea_nxt = cea[beg]; }

    for (int p = beg; p < end; p++) {
        int s = s_nxt; float ea = ea_nxt;
        if (p + 1 < end) { s_nxt = csrc[p + 1]; ea_nxt = cea[p + 1]; }

        float4 a0 = *(const float4*)&xl[s * 256 + c0];
        float4 a1 = *(const float4*)&xl[s * 256 + c0 + 4];

        float v0 = a0.x + xr0.x + ea * we0.x;
        float v1 = a0.y + xr0.y + ea * we0.y;
        float v2 = a0.z + xr0.z + ea * we0.z;
        float v3 = a0.w + xr0.w + ea * we0.w;
        float v4 = a1.x + xr1.x + ea * we1.x;
        float v5 = a1.y + xr1.y + ea * we1.y;
        float v6 = a1.z + xr1.z + ea * we1.z;
        float v7 = a1.w + xr1.w + ea * we1.w;
        v0 = (v0 > 0.f) ? v0 : 0.2f * v0;
        v1 = (v1 > 0.f) ? v1 : 0.2f * v1;
        v2 = (v2 > 0.f) ? v2 : 0.2f * v2;
        v3 = (v3 > 0.f) ? v3 : 0.2f * v3;
        v4 = (v4 > 0.f) ? v4 : 0.2f * v4;
        v5 = (v5 > 0.f) ? v5 : 0.2f * v5;
        v6 = (v6 > 0.f) ? v6 : 0.2f * v6;
        v7 = (v7 > 0.f) ? v7 : 0.2f * v7;

        float part = v0 * at0.x + v1 * at0.y + v2 * at0.z + v3 * at0.w
                   + v4 * at1.x + v5 * at1.y + v6 * at1.z + v7 * at1.w;
        part += __shfl_xor_sync(0xffffffffu, part, 1);
        part += __shfl_xor_sync(0xffffffffu, part, 2);
        part += __shfl_xor_sync(0xffffffffu, part, 4);
        float l = part;

        float m_new = fmaxf(m, l);
        float scale = __expf(m - m_new);
        float w = __expf(l - m_new);
        den = den * scale + w;
        acc[0] = acc[0] * scale + w * a0.x;
        acc[1] = acc[1] * scale + w * a0.y;
        acc[2] = acc[2] * scale + w * a0.z;
        acc[3] = acc[3] * scale + w * a0.w;
        acc[4] = acc[4] * scale + w * a1.x;
        acc[5] = acc[5] * scale + w * a1.y;
        acc[6] = acc[6] * scale + w * a1.z;
        acc[7] = acc[7] * scale + w * a1.w;
        m = m_new;
    }

    float inv = 1.f / (den + 1e-16f);
    float4 b0 = *(const float4*)&bias[c0];
    float4 b1 = *(const float4*)&bias[c0 + 4];
    float o[8];
    o[0] = fmaxf(acc[0] * inv + b0.x, 0.f);
    o[1] = fmaxf(acc[1] * inv + b0.y, 0.f);
    o[2] = fmaxf(acc[2] * inv + b0.z, 0.f);
    o[3] = fmaxf(acc[3] * inv + b0.w, 0.f);
    o[4] = fmaxf(acc[4] * inv + b1.x, 0.f);
    o[5] = fmaxf(acc[5] * inv + b1.y, 0.f);
    o[6] = fmaxf(acc[6] * inv + b1.z, 0.f);
    o[7] = fmaxf(acc[7] * inv + b1.w, 0.f);
    if (ROUND) {
#pragma unroll
        for (int i = 0; i < 8; i++) o[i] = round_tf32(o[i]);
    }
    *(float4*)&h_out[d * 256 + c0]     = make_float4(o[0], o[1], o[2], o[3]);
    *(float4*)&h_out[d * 256 + c0 + 4] = make_float4(o[4], o[5], o[6], o[7]);
}

// ---------------- mean pool (batch sorted) ----------------
__global__ void pool_kernel(const float* __restrict__ h, const int* __restrict__ batch,
                            float* __restrict__ sums, float* __restrict__ cnt) {
    int c = threadIdx.x;
    int n0 = blockIdx.x * 64;
    if (n0 >= NN) return;
    int cur = batch[n0];
    float acc = 0.f, fc = 0.f;
    for (int i = 0; i < 64; i++) {
        int node = n0 + i;
        if (node >= NN) break;
        int b = batch[node];
        if (b != cur) {
            atomicAdd(&sums[cur * 256 + c], acc);
            if (c == 0) atomicAdd(&cnt[cur], fc);
            acc = 0.f; fc = 0.f; cur = b;
        }
        acc += h[node * 256 + c];
        fc += 1.f;
    }
    atomicAdd(&sums[cur * 256 + c], acc);
    if (c == 0) atomicAdd(&cnt[cur], fc);
}

// ---------------- MLP head (also re-zeroes sums/cnt for next replay) ----------------
__global__ void head_kernel(float* __restrict__ sums, float* __restrict__ cnt,
                            const float* __restrict__ Wp1, const float* __restrict__ bp1,
                            const float* __restrict__ lng, const float* __restrict__ lnb,
                            const float* __restrict__ Wp2, const float* __restrict__ bp2,
                            const float* __restrict__ Wh, const float* __restrict__ bh,
                            float* __restrict__ out) {
    __shared__ float pool[256];
    __shared__ float pbuf[128];
    __shared__ float qbuf[64];
    __shared__ float redbuf[4];
    int g = blockIdx.x, t = threadIdx.x;
    float cn = fmaxf(cnt[g], 1.f);
    pool[t] = sums[g * 256 + t] / cn;
    pool[t + 128] = sums[g * 256 + 128 + t] / cn;
    sums[g * 256 + t] = 0.f;
    sums[g * 256 + 128 + t] = 0.f;
    if (t == 0) cnt[g] = 0.f;
    __syncthreads();

    float acc = bp1[t];
#pragma unroll 4
    for (int k = 0; k < 256; k++) acc += pool[k] * Wp1[k * 128 + t];

    float s = acc;
#pragma unroll
    for (int o = 16; o > 0; o >>= 1) s += __shfl_xor_sync(0xffffffffu, s, o);
    if ((t & 31) == 0) redbuf[t >> 5] = s;
    __syncthreads();
    float mu = (redbuf[0] + redbuf[1] + redbuf[2] + redbuf[3]) * (1.f / 128.f);
    __syncthreads();

    float dv = (acc - mu) * (acc - mu);
#pragma unroll
    for (int o = 16; o > 0; o >>= 1) dv += __shfl_xor_sync(0xffffffffu, dv, o);
    if ((t & 31) == 0) redbuf[t >> 5] = dv;
    __syncthreads();
    float var = (redbuf[0] + redbuf[1] + redbuf[2] + redbuf[3]) * (1.f / 128.f);

    float v = (acc - mu) * rsqrtf(var + 1e-5f) * lng[t] + lnb[t];
    pbuf[t] = fmaxf(v, 0.f);
    __syncthreads();

    if (t < 64) {
        float a = bp2[t];
#pragma unroll 4
        for (int k = 0; k < 128; k++) a += pbuf[k] * Wp2[k * 64 + t];
        qbuf[t] = fmaxf(a, 0.f);
    }
    __syncthreads();

    if (t < 32) {
        float a = qbuf[t] * Wh[t] + qbuf[t + 32] * Wh[t + 32];
#pragma unroll
        for (int o = 16; o > 0; o >>= 1) a += __shfl_xor_sync(0xffffffffu, a, o);
        if (t == 0) out[g] = a + bh[0];
    }
}

// ---------------- launch ----------------
static const int SMEM_K64  = 2 * STAGEF * 4;   // 2 stages = 73728 B
static const int SMEM_K256 = 3 * STAGEF * 4;   // 3 stages = 110592 B

extern "C" void kernel_launch(void* const* d_in, const int* in_sizes, int n_in,
                              void* d_out, int out_size) {
    const float* x       = (const float*)d_in[0];
    const float* eattr   = (const float*)d_in[1];
    const int*   src     = (const int*)d_in[2];
    const int*   dst     = (const int*)d_in[3];
    const int*   batch   = (const int*)d_in[4];
    const float* W_enc   = (const float*)d_in[5];
    const float* b_enc   = (const float*)d_in[6];
    const float* g1_Wl   = (const float*)d_in[7];
    const float* g1_bl   = (const float*)d_in[8];
    const float* g1_Wr   = (const float*)d_in[9];
    const float* g1_br   = (const float*)d_in[10];
    const float* g1_We   = (const float*)d_in[11];
    const float* g1_att  = (const float*)d_in[12];
    const float* g1_bias = (const float*)d_in[13];
    const float* g2_Wl   = (const float*)d_in[14];
    const float* g2_bl   = (const float*)d_in[15];
    const float* g2_Wr   = (const float*)d_in[16];
    const float* g2_br   = (const float*)d_in[17];
    const float* g2_We   = (const float*)d_in[18];
    const float* g2_att  = (const float*)d_in[19];
    const float* g2_bias = (const float*)d_in[20];
    const float* W_p1    = (const float*)d_in[21];
    const float* b_p1    = (const float*)d_in[22];
    const float* ln_g    = (const float*)d_in[23];
    const float* ln_b    = (const float*)d_in[24];
    const float* W_p2    = (const float*)d_in[25];
    const float* b_p2    = (const float*)d_in[26];
    const float* W_head  = (const float*)d_in[27];
    const float* b_head  = (const float*)d_in[28];
    float* out = (float*)d_out;

    float *h0, *xl, *xr, *h1, *sums, *cnt, *wt, *cea;
    int *rowptr, *cnts, *cursor, *csrc, *bsums;
    cudaGetSymbolAddress((void**)&h0,     g_h0);
    cudaGetSymbolAddress((void**)&xl,     g_xl);
    cudaGetSymbolAddress((void**)&xr,     g_xr);
    cudaGetSymbolAddress((void**)&h1,     g_h1);
    cudaGetSymbolAddress((void**)&sums,   g_sums);
    cudaGetSymbolAddress((void**)&cnt,    g_cnt);
    cudaGetSymbolAddress((void**)&wt,     g_wt);
    cudaGetSymbolAddress((void**)&rowptr, g_rowptr);
    cudaGetSymbolAddress((void**)&cnts,   g_cnts);
    cudaGetSymbolAddress((void**)&cursor, g_cursor);
    cudaGetSymbolAddress((void**)&csrc,   g_csrc);
    cudaGetSymbolAddress((void**)&cea,    g_cea);
    cudaGetSymbolAddress((void**)&bsums,  g_bsums);

    cudaFuncSetAttribute(mma_lr_kernel<64>,
                         cudaFuncAttributeMaxDynamicSharedMemorySize, SMEM_K64);
    cudaFuncSetAttribute(mma_lr_kernel<256>,
                         cudaFuncAttributeMaxDynamicSharedMemorySize, SMEM_K256);

    const int MT = (NN + 127) / 128;
    dim3 gemm_grid(MT, 4);
    const int NB_SCAN = (NN + 1023) / 1024;
    const int EW_GRID = (NN + 7) / 8;

    // harness adds 2 launches before these; ncu -s 5 -c 1 captures my index 3.
    enc_kernel<<<(NN * 64 + 255) / 256, 256>>>(x, W_enc, b_enc, h0);                   // 0
    build_wt_kernel<<<(512 * 64 + 255) / 256, 256>>>(g1_Wl, g1_Wr, wt, 64);            // 1
    hist_kernel<<<(EE + 255) / 256, 256>>>(dst, cnts);                                 // 2
    mma_lr_kernel<64><<<gemm_grid, 256, SMEM_K64>>>(h0, wt, g1_bl, g1_br, xl, xr, NN); // 3 <- profiled
    scan1_kernel<<<NB_SCAN, 1024>>>(cnts, rowptr, bsums);                              // 4
    scan2_kernel<<<1, 128>>>(bsums, NB_SCAN);                                          // 5
    scan3_kernel<<<NB_SCAN, 1024>>>(rowptr, bsums, cursor);                            // 6
    fillcol_kernel<<<(EE + 255) / 256, 256>>>(dst, src, eattr, cursor, csrc, cea);     // 7

    edge_fused_kernel<true><<<EW_GRID, 256>>>(xl, xr, g1_We, g1_att,
                                              rowptr, csrc, cea, g1_bias, h1);

    build_wt_kernel<<<(512 * 256 + 255) / 256, 256>>>(g2_Wl, g2_Wr, wt, 256);
    mma_lr_kernel<256><<<gemm_grid, 256, SMEM_K256>>>(h1, wt, g2_bl, g2_br, xl, xr, NN);
    edge_fused_kernel<false><<<EW_GRID, 256>>>(xl, xr, g2_We, g2_att,
                                               rowptr, csrc, cea, g2_bias, h1);

    pool_kernel<<<(NN + 63) / 64, 256>>>(h1, batch, sums, cnt);
    head_kernel<<<GG, 128>>>(sums, cnt, W_p1, b_p1, ln_g, ln_b, W_p2, b_p2, W_head, b_head, out);
}

// round 11
// speedup vs baseline: 1.0567x; 1.0116x over previous
#include <cuda_runtime.h>
#include <cuda_bf16.h>
#include <math.h>
#include <cstdint>

#define NN 100000
#define EE 400000
#define GG 64

// ---------------- scratch (device globals; no allocation allowed) ----------------
__device__ float g_h0[NN * 64];        // encoder output (tf32-rounded values)
__device__ float g_xl[NN * 256];       // source-side transform
__device__ float g_xr[NN * 256];       // target-side transform
__device__ float g_h1[NN * 256];       // layer-1 output (tf32-rounded)
__device__ float g_sums[GG * 256];     // pooled sums (zeroed by head_kernel after use)
__device__ float g_cnt[GG];            // node counts (zeroed by head_kernel after use)
__device__ float g_wt[512 * 256];      // fused transposed weights [512 n-rows, K] (tf32-rounded)
// CSR over dst (built once per launch; dst shared by both layers)
__device__ int   g_rowptr[NN + 1];
__device__ int   g_cnts[NN];           // histogram (self-cleared by scan1 each run)
__device__ int   g_cursor[NN];         // write cursors (seeded by scan3 each run)
__device__ int   g_csrc[EE];           // src id per CSR slot
__device__ float g_cea[EE];            // edge attr per CSR slot
__device__ int   g_bsums[128];

// ---------------- small utils ----------------
__device__ __forceinline__ uint32_t cvt_tf32(float x) {
    uint32_t r;
    asm("cvt.rna.tf32.f32 %0, %1;" : "=r"(r) : "f"(x));
    return r;
}
__device__ __forceinline__ float round_tf32(float x) {
    return __uint_as_float(cvt_tf32(x));
}
__device__ __forceinline__ uint32_t smem_u32(const void* p) {
    uint32_t a;
    asm("{ .reg .u64 t; cvta.to.shared.u64 t, %1; cvt.u32.u64 %0, t; }" : "=r"(a) : "l"(p));
    return a;
}
__device__ __forceinline__ void cp16(uint32_t saddr, const void* g, bool pred) {
    int sz = pred ? 16 : 0;
    asm volatile("cp.async.cg.shared.global [%0], [%1], 16, %2;"
                 :: "r"(saddr), "l"(g), "r"(sz));
}
__device__ __forceinline__ void red4(float* p, float a, float b, float c, float d) {
    asm volatile("red.global.add.v4.f32 [%0], {%1, %2, %3, %4};"
                 :: "l"(p), "f"(a), "f"(b), "f"(c), "f"(d) : "memory");
}
__device__ __forceinline__ void mma_tf32_16x8x8(float* d, const uint32_t* a, const uint32_t* b) {
    asm volatile(
        "mma.sync.aligned.m16n8k8.row.col.f32.tf32.tf32.f32 "
        "{%0,%1,%2,%3}, {%4,%5,%6,%7}, {%8,%9}, {%0,%1,%2,%3};"
        : "+f"(d[0]), "+f"(d[1]), "+f"(d[2]), "+f"(d[3])
        : "r"(a[0]), "r"(a[1]), "r"(a[2]), "r"(a[3]), "r"(b[0]), "r"(b[1]));
}

// ---------------- CSR build over dst ----------------
__global__ void hist_kernel(const int* __restrict__ dst, int* __restrict__ cnts) {
    int e = blockIdx.x * blockDim.x + threadIdx.x;
    if (e < EE) atomicAdd(&cnts[dst[e]], 1);
}
__global__ void scan1_kernel(int* __restrict__ cnts, int* __restrict__ rowptr,
                             int* __restrict__ bsums) {
    __shared__ int buf[2][1024];
    int b = blockIdx.x, t = threadIdx.x;
    int i = b * 1024 + t;
    int myc = (i < NN) ? cnts[i] : 0;
    if (i < NN) cnts[i] = 0;             // self-clean for next replay
    buf[0][t] = myc;
    __syncthreads();
    int cur = 0;
#pragma unroll
    for (int off = 1; off < 1024; off <<= 1) {
        int x = buf[cur][t];
        if (t >= off) x += buf[cur][t - off];
        buf[cur ^ 1][t] = x;
        cur ^= 1;
        __syncthreads();
    }
    int inc = buf[cur][t];
    if (i < NN) rowptr[i + 1] = inc;
    if (t == 1023) bsums[b] = inc;
}
__global__ void scan2_kernel(int* __restrict__ bsums, int nb) {
    __shared__ int buf[2][128];
    int t = threadIdx.x;
    int v = (t < nb) ? bsums[t] : 0;
    buf[0][t] = v;
    __syncthreads();
    int cur = 0;
#pragma unroll
    for (int off = 1; off < 128; off <<= 1) {
        int x = buf[cur][t];
        if (t >= off) x += buf[cur][t - off];
        buf[cur ^ 1][t] = x;
        cur ^= 1;
        __syncthreads();
    }
    if (t < nb) bsums[t] = buf[cur][t] - v;   // exclusive
}
__global__ void scan3_kernel(int* __restrict__ rowptr, const int* __restrict__ bsums,
                             int* __restrict__ cursor) {
    int b = blockIdx.x, t = threadIdx.x;
    int i = b * 1024 + t;
    if (i < NN) {
        int rp1 = rowptr[i + 1] + bsums[b];
        rowptr[i + 1] = rp1;
        if (i + 1 < NN) cursor[i + 1] = rp1;
    }
    if (i == 0) { rowptr[0] = 0; cursor[0] = 0; }
}
__global__ void fillcol_kernel(const int* __restrict__ dst, const int* __restrict__ src,
                               const float* __restrict__ eattr, int* __restrict__ cursor,
                               int* __restrict__ csrc, float* __restrict__ cea) {
    int e = blockIdx.x * blockDim.x + threadIdx.x;
    if (e >= EE) return;
    int pos = atomicAdd(&cursor[dst[e]], 1);
    csrc[pos] = src[e];
    cea[pos] = eattr[e];
}

// ---------------- tf32 MMA GEMM via cp.async (round-7 proven config) ----------------
#define ROWPITCH 36
#define STAGEF (256 * ROWPITCH)          // A(128 rows) + B(128 rows) per stage

template <int K>
__global__ void __launch_bounds__(256, 2)
mma_lr_kernel(const float* __restrict__ X, const float* __restrict__ WT,
              const float* __restrict__ bl, const float* __restrict__ br,
              float* __restrict__ xl, float* __restrict__ xr, int n) {
    extern __shared__ float smf[];
    constexpr int NC = K / 32;

    int tid = threadIdx.x;
    int wid = tid >> 5, lane = tid & 31;
    int wm = wid & 1, wn = wid >> 1;
    int tg = lane >> 2, tig = lane & 3;
    int row0 = blockIdx.x * 128;
    int nbase = blockIdx.y * 128;        // fused-row base in WT (0..511)
    uint32_t sbase = smem_u32(smf);

    auto issue_chunk = [&](int c) {
        int s = c & 1;
        uint32_t a_s = sbase + s * (STAGEF * 4);
        uint32_t b_s = a_s + 128 * ROWPITCH * 4;
#pragma unroll
        for (int j = 0; j < 4; j++) {
            int i = tid + j * 256;
            int r = i >> 3, q = i & 7;
            int row = row0 + r;
            bool ok = row < n;
            const float* ga = ok ? &X[(size_t)row * K + c * 32 + q * 4] : X;
            cp16(a_s + (uint32_t)(r * ROWPITCH + q * 4) * 4, ga, ok);
            cp16(b_s + (uint32_t)(r * ROWPITCH + q * 4) * 4,
                 &WT[(size_t)(nbase + r) * K + c * 32 + q * 4], true);
        }
        asm volatile("cp.async.commit_group;");
    };

    float d[4][4][4];
#pragma unroll
    for (int i = 0; i < 4; i++)
#pragma unroll
        for (int j = 0; j < 4; j++)
#pragma unroll
            for (int q = 0; q < 4; q++) d[i][j][q] = 0.f;

    issue_chunk(0);
    if (NC > 1) issue_chunk(1);

#pragma unroll
    for (int c = 0; c < NC; c++) {
        if (c < NC - 1) asm volatile("cp.async.wait_group 1;");
        else            asm volatile("cp.async.wait_group 0;");
        __syncthreads();

        int s = c & 1;
        const uint32_t* As = (const uint32_t*)(smf + s * STAGEF);
        const uint32_t* Bs = As + 128 * ROWPITCH;
#pragma unroll
        for (int ks = 0; ks < 4; ks++) {
            uint32_t a[4][4], b[4][2];
#pragma unroll
            for (int mt = 0; mt < 4; mt++) {
                const uint32_t* p = As + (wm * 64 + mt * 16 + tg) * ROWPITCH + ks * 8 + tig;
                a[mt][0] = p[0];
                a[mt][1] = p[8 * ROWPITCH];
                a[mt][2] = p[4];
                a[mt][3] = p[8 * ROWPITCH + 4];
            }
#pragma unroll
            for (int nt = 0; nt < 4; nt++) {
                const uint32_t* p = Bs + (wn * 32 + nt * 8 + tg) * ROWPITCH + ks * 8 + tig;
                b[nt][0] = p[0];
                b[nt][1] = p[4];
            }
#pragma unroll
            for (int mt = 0; mt < 4; mt++)
#pragma unroll
                for (int nt = 0; nt < 4; nt++)
                    mma_tf32_16x8x8(d[mt][nt], a[mt], b[nt]);
        }

        if (c + 2 < NC) {
            __syncthreads();
            issue_chunk(c + 2);
        }
    }

    bool is_l = (nbase < 256);
    float* Y = is_l ? xl : xr;
    const float* bias = is_l ? bl : br;
    int colb = nbase & 255;
#pragma unroll
    for (int mt = 0; mt < 4; mt++) {
        int r0 = row0 + wm * 64 + mt * 16 + tg;
#pragma unroll
        for (int nt = 0; nt < 4; nt++) {
            int col = colb + wn * 32 + nt * 8 + 2 * tig;
            float2 bv = *(const float2*)&bias[col];
            if (r0 < n)
                *(float2*)&Y[(size_t)r0 * 256 + col] =
                    make_float2(d[mt][nt][0] + bv.x, d[mt][nt][1] + bv.y);
            if (r0 + 8 < n)
                *(float2*)&Y[(size_t)(r0 + 8) * 256 + col] =
                    make_float2(d[mt][nt][2] + bv.x, d[mt][nt][3] + bv.y);
        }
    }
}

// build WT[512,K] K-major from Wl/Wr [K,256]; pre-round to tf32
__global__ void build_wt_kernel(const float* __restrict__ Wl, const float* __restrict__ Wr,
                                float* __restrict__ WT, int K) {
    int idx = blockIdx.x * blockDim.x + threadIdx.x;
    if (idx >= 512 * K) return;
    int nrow = idx / K, k = idx - nrow * K;
    float v = (nrow < 256) ? Wl[k * 256 + nrow] : Wr[k * 256 + (nrow - 256)];
    WT[idx] = round_tf32(v);
}

// ---------------- encoder (output tf32-rounded) ----------------
__global__ void enc_kernel(const float* __restrict__ x, const float* __restrict__ W,
                           const float* __restrict__ b, float* __restrict__ h0) {
    int idx = blockIdx.x * blockDim.x + threadIdx.x;
    if (idx >= NN * 64) return;
    int i = idx >> 6;
    int c = idx & 63;
    float acc = b[c];
#pragma unroll
    for (int k = 0; k < 8; k++) acc += x[i * 8 + k] * W[k * 64 + c];
    h0[idx] = round_tf32(fmaxf(acc, 0.f));
}

// ---------------- shared edge-aggregation core (one warp per dst node) ----------------
struct EdgeOut { float o[8]; };

__device__ __forceinline__ EdgeOut edge_aggregate(
    const float* __restrict__ xl, const float* __restrict__ xr,
    const float* __restrict__ We, const float* __restrict__ att,
    const int* __restrict__ rowptr,
    const int* __restrict__ csrc, const float* __restrict__ cea,
    const float* __restrict__ bias, int d, int lane) {
    int c0 = lane * 8;

    float4 xr0 = *(const float4*)&xr[d * 256 + c0];
    float4 xr1 = *(const float4*)&xr[d * 256 + c0 + 4];
    float4 we0 = *(const float4*)&We[c0];
    float4 we1 = *(const float4*)&We[c0 + 4];
    float4 at0 = *(const float4*)&att[c0];
    float4 at1 = *(const float4*)&att[c0 + 4];

    int beg = rowptr[d], end = rowptr[d + 1];
    float m = -INFINITY, den = 0.f;
    float acc[8] = {0.f, 0.f, 0.f, 0.f, 0.f, 0.f, 0.f, 0.f};

    int s_nxt = 0; float ea_nxt = 0.f;
    if (beg < end) { s_nxt = csrc[beg]; ea_nxt = cea[beg]; }

    for (int p = beg; p < end; p++) {
        int s = s_nxt; float ea = ea_nxt;
        if (p + 1 < end) { s_nxt = csrc[p + 1]; ea_nxt = cea[p + 1]; }

        float4 a0 = *(const float4*)&xl[s * 256 + c0];
        float4 a1 = *(const float4*)&xl[s * 256 + c0 + 4];

        float v0 = a0.x + xr0.x + ea * we0.x;
        float v1 = a0.y + xr0.y + ea * we0.y;
        float v2 = a0.z + xr0.z + ea * we0.z;
        float v3 = a0.w + xr0.w + ea * we0.w;
        float v4 = a1.x + xr1.x + ea * we1.x;
        float v5 = a1.y + xr1.y + ea * we1.y;
        float v6 = a1.z + xr1.z + ea * we1.z;
        float v7 = a1.w + xr1.w + ea * we1.w;
        v0 = (v0 > 0.f) ? v0 : 0.2f * v0;
        v1 = (v1 > 0.f) ? v1 : 0.2f * v1;
        v2 = (v2 > 0.f) ? v2 : 0.2f * v2;
        v3 = (v3 > 0.f) ? v3 : 0.2f * v3;
        v4 = (v4 > 0.f) ? v4 : 0.2f * v4;
        v5 = (v5 > 0.f) ? v5 : 0.2f * v5;
        v6 = (v6 > 0.f) ? v6 : 0.2f * v6;
        v7 = (v7 > 0.f) ? v7 : 0.2f * v7;

        float part = v0 * at0.x + v1 * at0.y + v2 * at0.z + v3 * at0.w
                   + v4 * at1.x + v5 * at1.y + v6 * at1.z + v7 * at1.w;
        part += __shfl_xor_sync(0xffffffffu, part, 1);
        part += __shfl_xor_sync(0xffffffffu, part, 2);
        part += __shfl_xor_sync(0xffffffffu, part, 4);
        float l = part;

        float m_new = fmaxf(m, l);
        float scale = __expf(m - m_new);
        float w = __expf(l - m_new);
        den = den * scale + w;
        acc[0] = acc[0] * scale + w * a0.x;
        acc[1] = acc[1] * scale + w * a0.y;
        acc[2] = acc[2] * scale + w * a0.z;
        acc[3] = acc[3] * scale + w * a0.w;
        acc[4] = acc[4] * scale + w * a1.x;
        acc[5] = acc[5] * scale + w * a1.y;
        acc[6] = acc[6] * scale + w * a1.z;
        acc[7] = acc[7] * scale + w * a1.w;
        m = m_new;
    }

    float inv = 1.f / (den + 1e-16f);
    float4 b0 = *(const float4*)&bias[c0];
    float4 b1 = *(const float4*)&bias[c0 + 4];
    EdgeOut r;
    r.o[0] = fmaxf(acc[0] * inv + b0.x, 0.f);
    r.o[1] = fmaxf(acc[1] * inv + b0.y, 0.f);
    r.o[2] = fmaxf(acc[2] * inv + b0.z, 0.f);
    r.o[3] = fmaxf(acc[3] * inv + b0.w, 0.f);
    r.o[4] = fmaxf(acc[4] * inv + b1.x, 0.f);
    r.o[5] = fmaxf(acc[5] * inv + b1.y, 0.f);
    r.o[6] = fmaxf(acc[6] * inv + b1.z, 0.f);
    r.o[7] = fmaxf(acc[7] * inv + b1.w, 0.f);
    return r;
}

// layer 1: write h1 (tf32-rounded, feeds the next GEMM)
__global__ void __launch_bounds__(256)
edge_fused_kernel(const float* __restrict__ xl, const float* __restrict__ xr,
                  const float* __restrict__ We, const float* __restrict__ att,
                  const int* __restrict__ rowptr,
                  const int* __restrict__ csrc, const float* __restrict__ cea,
                  const float* __restrict__ bias, float* __restrict__ h_out) {
    int d = blockIdx.x * 8 + (threadIdx.x >> 5);
    int lane = threadIdx.x & 31;
    if (d >= NN) return;
    EdgeOut r = edge_aggregate(xl, xr, We, att, rowptr, csrc, cea, bias, d, lane);
    int c0 = lane * 8;
#pragma unroll
    for (int i = 0; i < 8; i++) r.o[i] = round_tf32(r.o[i]);
    *(float4*)&h_out[d * 256 + c0]     = make_float4(r.o[0], r.o[1], r.o[2], r.o[3]);
    *(float4*)&h_out[d * 256 + c0 + 4] = make_float4(r.o[4], r.o[5], r.o[6], r.o[7]);
}

// layer 2: fused mean-pool — no h1 write/read. CTA-level smem accumulation keyed
// by graph (batch sorted -> <=2 graphs per 8-node CTA almost always; fallback RED).
__global__ void __launch_bounds__(256)
edge_pool_kernel(const float* __restrict__ xl, const float* __restrict__ xr,
                 const float* __restrict__ We, const float* __restrict__ att,
                 const int* __restrict__ rowptr,
                 const int* __restrict__ csrc, const float* __restrict__ cea,
                 const float* __restrict__ bias, const int* __restrict__ batch,
                 float* __restrict__ sums, float* __restrict__ cnt) {
    __shared__ float p0[256], p1[256];
    __shared__ float c0s[2];
    __shared__ int gids[2];
    int t = threadIdx.x;
    int warp = t >> 5, lane = t & 31;
    int d0 = blockIdx.x * 8;
    int d = d0 + warp;

    if (t == 0) {
        int dl = d0 + 7; if (dl >= NN) dl = NN - 1;
        gids[0] = batch[d0 < NN ? d0 : NN - 1];
        gids[1] = batch[dl];
        c0s[0] = 0.f; c0s[1] = 0.f;
    }
    p0[t] = 0.f; p1[t] = 0.f;
    __syncthreads();

    if (d < NN) {
        EdgeOut r = edge_aggregate(xl, xr, We, att, rowptr, csrc, cea, bias, d, lane);
        int b = batch[d];
        int c0 = lane * 8;
        if (b == gids[0]) {
#pragma unroll
            for (int i = 0; i < 8; i++) atomicAdd(&p0[c0 + i], r.o[i]);
            if (lane == 0) atomicAdd(&c0s[0], 1.f);
        } else if (b == gids[1]) {
#pragma unroll
            for (int i = 0; i < 8; i++) atomicAdd(&p1[c0 + i], r.o[i]);
            if (lane == 0) atomicAdd(&c0s[1], 1.f);
        } else {
            // rare: a third graph inside the 8-node window
            red4(&sums[b * 256 + c0], r.o[0], r.o[1], r.o[2], r.o[3]);
            red4(&sums[b * 256 + c0 + 4], r.o[4], r.o[5], r.o[6], r.o[7]);
            if (lane == 0) atomicAdd(&cnt[b], 1.f);
        }
    }
    __syncthreads();

    int g0 = gids[0], g1 = gids[1];
    if (t < 64) {
        float4 v = *(const float4*)&p0[t * 4];
        red4(&sums[g0 * 256 + t * 4], v.x, v.y, v.z, v.w);
    } else if (t < 128 && g1 != g0) {
        int u = t - 64;
        float4 v = *(const float4*)&p1[u * 4];
        red4(&sums[g1 * 256 + u * 4], v.x, v.y, v.z, v.w);
    }
    if (t == 128) atomicAdd(&cnt[g0], c0s[0]);
    if (t == 129 && g1 != g0) atomicAdd(&cnt[g1], c0s[1]);
}

// ---------------- MLP head (also re-zeroes sums/cnt for next replay) ----------------
__global__ void head_kernel(float* __restrict__ sums, float* __restrict__ cnt,
                            const float* __restrict__ Wp1, const float* __restrict__ bp1,
                            const float* __restrict__ lng, const float* __restrict__ lnb,
                            const float* __restrict__ Wp2, const float* __restrict__ bp2,
                            const float* __restrict__ Wh, const float* __restrict__ bh,
                            float* __restrict__ out) {
    __shared__ float pool[256];
    __shared__ float pbuf[128];
    __shared__ float qbuf[64];
    __shared__ float redbuf[4];
    int g = blockIdx.x, t = threadIdx.x;
    float cn = fmaxf(cnt[g], 1.f);
    pool[t] = sums[g * 256 + t] / cn;
    pool[t + 128] = sums[g * 256 + 128 + t] / cn;
    sums[g * 256 + t] = 0.f;
    sums[g * 256 + 128 + t] = 0.f;
    if (t == 0) cnt[g] = 0.f;
    __syncthreads();

    float acc = bp1[t];
#pragma unroll 4
    for (int k = 0; k < 256; k++) acc += pool[k] * Wp1[k * 128 + t];

    float s = acc;
#pragma unroll
    for (int o = 16; o > 0; o >>= 1) s += __shfl_xor_sync(0xffffffffu, s, o);
    if ((t & 31) == 0) redbuf[t >> 5] = s;
    __syncthreads();
    float mu = (redbuf[0] + redbuf[1] + redbuf[2] + redbuf[3]) * (1.f / 128.f);
    __syncthreads();

    float dv = (acc - mu) * (acc - mu);
#pragma unroll
    for (int o = 16; o > 0; o >>= 1) dv += __shfl_xor_sync(0xffffffffu, dv, o);
    if ((t & 31) == 0) redbuf[t >> 5] = dv;
    __syncthreads();
    float var = (redbuf[0] + redbuf[1] + redbuf[2] + redbuf[3]) * (1.f / 128.f);

    float v = (acc - mu) * rsqrtf(var + 1e-5f) * lng[t] + lnb[t];
    pbuf[t] = fmaxf(v, 0.f);
    __syncthreads();

    if (t < 64) {
        float a = bp2[t];
#pragma unroll 4
        for (int k = 0; k < 128; k++) a += pbuf[k] * Wp2[k * 64 + t];
        qbuf[t] = fmaxf(a, 0.f);
    }
    __syncthreads();

    if (t < 32) {
        float a = qbuf[t] * Wh[t] + qbuf[t + 32] * Wh[t + 32];
#pragma unroll
        for (int o = 16; o > 0; o >>= 1) a += __shfl_xor_sync(0xffffffffu, a, o);
        if (t == 0) out[g] = a + bh[0];
    }
}

// ---------------- launch ----------------
static const int MMA_SMEM = 2 * STAGEF * 4;

extern "C" void kernel_launch(void* const* d_in, const int* in_sizes, int n_in,
                              void* d_out, int out_size) {
    const float* x       = (const float*)d_in[0];
    const float* eattr   = (const float*)d_in[1];
    const int*   src     = (const int*)d_in[2];
    const int*   dst     = (const int*)d_in[3];
    const int*   batch   = (const int*)d_in[4];
    const float* W_enc   = (const float*)d_in[5];
    const float* b_enc   = (const float*)d_in[6];
    const float* g1_Wl   = (const float*)d_in[7];
    const float* g1_bl   = (const float*)d_in[8];
    const float* g1_Wr   = (const float*)d_in[9];
    const float* g1_br   = (const float*)d_in[10];
    const float* g1_We   = (const float*)d_in[11];
    const float* g1_att  = (const float*)d_in[12];
    const float* g1_bias = (const float*)d_in[13];
    const float* g2_Wl   = (const float*)d_in[14];
    const float* g2_bl   = (const float*)d_in[15];
    const float* g2_Wr   = (const float*)d_in[16];
    const float* g2_br   = (const float*)d_in[17];
    const float* g2_We   = (const float*)d_in[18];
    const float* g2_att  = (const float*)d_in[19];
    const float* g2_bias = (const float*)d_in[20];
    const float* W_p1    = (const float*)d_in[21];
    const float* b_p1    = (const float*)d_in[22];
    const float* ln_g    = (const float*)d_in[23];
    const float* ln_b    = (const float*)d_in[24];
    const float* W_p2    = (const float*)d_in[25];
    const float* b_p2    = (const float*)d_in[26];
    const float* W_head  = (const float*)d_in[27];
    const float* b_head  = (const float*)d_in[28];
    float* out = (float*)d_out;

    float *h0, *xl, *xr, *h1, *sums, *cnt, *wt, *cea;
    int *rowptr, *cnts, *cursor, *csrc, *bsums;
    cudaGetSymbolAddress((void**)&h0,     g_h0);
    cudaGetSymbolAddress((void**)&xl,     g_xl);
    cudaGetSymbolAddress((void**)&xr,     g_xr);
    cudaGetSymbolAddress((void**)&h1,     g_h1);
    cudaGetSymbolAddress((void**)&sums,   g_sums);
    cudaGetSymbolAddress((void**)&cnt,    g_cnt);
    cudaGetSymbolAddress((void**)&wt,     g_wt);
    cudaGetSymbolAddress((void**)&rowptr, g_rowptr);
    cudaGetSymbolAddress((void**)&cnts,   g_cnts);
    cudaGetSymbolAddress((void**)&cursor, g_cursor);
    cudaGetSymbolAddress((void**)&csrc,   g_csrc);
    cudaGetSymbolAddress((void**)&cea,    g_cea);
    cudaGetSymbolAddress((void**)&bsums,  g_bsums);

    cudaFuncSetAttribute(mma_lr_kernel<64>,
                         cudaFuncAttributeMaxDynamicSharedMemorySize, MMA_SMEM);
    cudaFuncSetAttribute(mma_lr_kernel<256>,
                         cudaFuncAttributeMaxDynamicSharedMemorySize, MMA_SMEM);

    const int MT = (NN + 127) / 128;
    dim3 gemm_grid(MT, 4);
    const int NB_SCAN = (NN + 1023) / 1024;
    const int EW_GRID = (NN + 7) / 8;

    // harness adds 2 launches before these; ncu -s 5 -c 1 captures my index 3.
    enc_kernel<<<(NN * 64 + 255) / 256, 256>>>(x, W_enc, b_enc, h0);                   // 0
    build_wt_kernel<<<(512 * 64 + 255) / 256, 256>>>(g1_Wl, g1_Wr, wt, 64);            // 1
    hist_kernel<<<(EE + 255) / 256, 256>>>(dst, cnts);                                 // 2
    mma_lr_kernel<64><<<gemm_grid, 256, MMA_SMEM>>>(h0, wt, g1_bl, g1_br, xl, xr, NN); // 3 <- profiled
    scan1_kernel<<<NB_SCAN, 1024>>>(cnts, rowptr, bsums);                              // 4
    scan2_kernel<<<1, 128>>>(bsums, NB_SCAN);                                          // 5
    scan3_kernel<<<NB_SCAN, 1024>>>(rowptr, bsums, cursor);                            // 6
    fillcol_kernel<<<(EE + 255) / 256, 256>>>(dst, src, eattr, cursor, csrc, cea);     // 7

    edge_fused_kernel<<<EW_GRID, 256>>>(xl, xr, g1_We, g1_att,
                                        rowptr, csrc, cea, g1_bias, h1);

    build_wt_kernel<<<(512 * 256 + 255) / 256, 256>>>(g2_Wl, g2_Wr, wt, 256);
    mma_lr_kernel<256><<<gemm_grid, 256, MMA_SMEM>>>(h1, wt, g2_bl, g2_br, xl, xr, NN);
    edge_pool_kernel<<<EW_GRID, 256>>>(xl, xr, g2_We, g2_att,
                                       rowptr, csrc, cea, g2_bias, batch, sums, cnt);

    head_kernel<<<GG, 128>>>(sums, cnt, W_p1, b_p1, ln_g, ln_b, W_p2, b_p2, W_head, b_head, out);
}

// round 13
// speedup vs baseline: 1.0806x; 1.0227x over previous
#include <cuda_runtime.h>
#include <cuda_bf16.h>
#include <math.h>
#include <cstdint>

#define NN 100000
#define EE 400000
#define GG 64

// ---------------- scratch (device globals; no allocation allowed) ----------------
__device__ float g_h0[NN * 64];        // encoder output (tf32-rounded values)
__device__ float g_xl[NN * 256];       // source-side transform
__device__ float g_xr[NN * 256];       // target-side transform
__device__ float g_h1[NN * 256];       // layer-1 output (tf32-rounded)
__device__ float g_sums[GG * 256];     // pooled sums (zeroed by head_kernel after use)
__device__ float g_cnt[GG];            // node counts (zeroed by head_kernel after use)
__device__ float g_wt[512 * 256];      // fused transposed weights [512 n-rows, K] (tf32-rounded)
// CSR over dst (built once per launch; dst shared by both layers)
__device__ int   g_rowptr[NN + 1];
__device__ int   g_cnts[NN];           // histogram (self-cleared by scan1 each run)
__device__ int   g_cursor[NN];         // write cursors (seeded by scan3 each run)
__device__ int   g_csrc[EE];           // src id per CSR slot
__device__ float g_cea[EE];            // edge attr per CSR slot
__device__ int   g_bsums[128];

// ---------------- small utils ----------------
__device__ __forceinline__ uint32_t cvt_tf32(float x) {
    uint32_t r;
    asm("cvt.rna.tf32.f32 %0, %1;" : "=r"(r) : "f"(x));
    return r;
}
__device__ __forceinline__ float round_tf32(float x) {
    return __uint_as_float(cvt_tf32(x));
}
__device__ __forceinline__ uint32_t smem_u32(const void* p) {
    uint32_t a;
    asm("{ .reg .u64 t; cvta.to.shared.u64 t, %1; cvt.u32.u64 %0, t; }" : "=r"(a) : "l"(p));
    return a;
}
__device__ __forceinline__ void cp16(uint32_t saddr, const void* g, bool pred) {
    int sz = pred ? 16 : 0;
    asm volatile("cp.async.cg.shared.global [%0], [%1], 16, %2;"
                 :: "r"(saddr), "l"(g), "r"(sz));
}
__device__ __forceinline__ void red4(float* p, float a, float b, float c, float d) {
    asm volatile("red.global.add.v4.f32 [%0], {%1, %2, %3, %4};"
                 :: "l"(p), "f"(a), "f"(b), "f"(c), "f"(d) : "memory");
}
__device__ __forceinline__ void mma_tf32_16x8x8(float* d, const uint32_t* a, const uint32_t* b) {
    asm volatile(
        "mma.sync.aligned.m16n8k8.row.col.f32.tf32.tf32.f32 "
        "{%0,%1,%2,%3}, {%4,%5,%6,%7}, {%8,%9}, {%0,%1,%2,%3};"
        : "+f"(d[0]), "+f"(d[1]), "+f"(d[2]), "+f"(d[3])
        : "r"(a[0]), "r"(a[1]), "r"(a[2]), "r"(a[3]), "r"(b[0]), "r"(b[1]));
}

// ---------------- CSR build over dst ----------------
__global__ void hist_kernel(const int* __restrict__ dst, int* __restrict__ cnts) {
    int e = blockIdx.x * blockDim.x + threadIdx.x;
    if (e < EE) atomicAdd(&cnts[dst[e]], 1);
}
__global__ void scan1_kernel(int* __restrict__ cnts, int* __restrict__ rowptr,
                             int* __restrict__ bsums) {
    __shared__ int buf[2][1024];
    int b = blockIdx.x, t = threadIdx.x;
    int i = b * 1024 + t;
    int myc = (i < NN) ? cnts[i] : 0;
    if (i < NN) cnts[i] = 0;             // self-clean for next replay
    buf[0][t] = myc;
    __syncthreads();
    int cur = 0;
#pragma unroll
    for (int off = 1; off < 1024; off <<= 1) {
        int x = buf[cur][t];
        if (t >= off) x += buf[cur][t - off];
        buf[cur ^ 1][t] = x;
        cur ^= 1;
        __syncthreads();
    }
    int inc = buf[cur][t];
    if (i < NN) rowptr[i + 1] = inc;
    if (t == 1023) bsums[b] = inc;
}
__global__ void scan2_kernel(int* __restrict__ bsums, int nb) {
    __shared__ int buf[2][128];
    int t = threadIdx.x;
    int v = (t < nb) ? bsums[t] : 0;
    buf[0][t] = v;
    __syncthreads();
    int cur = 0;
#pragma unroll
    for (int off = 1; off < 128; off <<= 1) {
        int x = buf[cur][t];
        if (t >= off) x += buf[cur][t - off];
        buf[cur ^ 1][t] = x;
        cur ^= 1;
        __syncthreads();
    }
    if (t < nb) bsums[t] = buf[cur][t] - v;   // exclusive
}
__global__ void scan3_kernel(int* __restrict__ rowptr, const int* __restrict__ bsums,
                             int* __restrict__ cursor) {
    int b = blockIdx.x, t = threadIdx.x;
    int i = b * 1024 + t;
    if (i < NN) {
        int rp1 = rowptr[i + 1] + bsums[b];
        rowptr[i + 1] = rp1;
        if (i + 1 < NN) cursor[i + 1] = rp1;
    }
    if (i == 0) { rowptr[0] = 0; cursor[0] = 0; }
}
__global__ void fillcol_kernel(const int* __restrict__ dst, const int* __restrict__ src,
                               const float* __restrict__ eattr, int* __restrict__ cursor,
                               int* __restrict__ csrc, float* __restrict__ cea) {
    int e = blockIdx.x * blockDim.x + threadIdx.x;
    if (e >= EE) return;
    int pos = atomicAdd(&cursor[dst[e]], 1);
    csrc[pos] = src[e];
    cea[pos] = eattr[e];
}

// ---------------- tf32 MMA GEMM via cp.async (round-7 config, strip-major grid) ----------------
// Grid (4, MT): blockIdx.x = N-strip (adjacent CTAs share the SAME A tile -> L2 reuse),
// blockIdx.y = M-tile. 128x128 CTA tile, 256 thr, 2 CTAs/SM.
#define ROWPITCH 36
#define STAGEF (256 * ROWPITCH)          // A(128 rows) + B(128 rows) per stage

template <int K>
__global__ void __launch_bounds__(256, 2)
mma_lr_kernel(const float* __restrict__ X, const float* __restrict__ WT,
              const float* __restrict__ bl, const float* __restrict__ br,
              float* __restrict__ xl, float* __restrict__ xr, int n) {
    extern __shared__ float smf[];
    constexpr int NC = K / 32;

    int tid = threadIdx.x;
    int wid = tid >> 5, lane = tid & 31;
    int wm = wid & 1, wn = wid >> 1;
    int tg = lane >> 2, tig = lane & 3;
    int row0 = blockIdx.y * 128;         // M-tile
    int nbase = blockIdx.x * 128;        // N-strip: fused-row base in WT (0..511)
    uint32_t sbase = smem_u32(smf);

    auto issue_chunk = [&](int c) {
        int s = c & 1;
        uint32_t a_s = sbase + s * (STAGEF * 4);
        uint32_t b_s = a_s + 128 * ROWPITCH * 4;
#pragma unroll
        for (int j = 0; j < 4; j++) {
            int i = tid + j * 256;
            int r = i >> 3, q = i & 7;
            int row = row0 + r;
            bool ok = row < n;
            const float* ga = ok ? &X[(size_t)row * K + c * 32 + q * 4] : X;
            cp16(a_s + (uint32_t)(r * ROWPITCH + q * 4) * 4, ga, ok);
            cp16(b_s + (uint32_t)(r * ROWPITCH + q * 4) * 4,
                 &WT[(size_t)(nbase + r) * K + c * 32 + q * 4], true);
        }
        asm volatile("cp.async.commit_group;");
    };

    float d[4][4][4];
#pragma unroll
    for (int i = 0; i < 4; i++)
#pragma unroll
        for (int j = 0; j < 4; j++)
#pragma unroll
            for (int q = 0; q < 4; q++) d[i][j][q] = 0.f;

    issue_chunk(0);
    if (NC > 1) issue_chunk(1);

#pragma unroll
    for (int c = 0; c < NC; c++) {
        if (c < NC - 1) asm volatile("cp.async.wait_group 1;");
        else            asm volatile("cp.async.wait_group 0;");
        __syncthreads();

        int s = c & 1;
        const uint32_t* As = (const uint32_t*)(smf + s * STAGEF);
        const uint32_t* Bs = As + 128 * ROWPITCH;
#pragma unroll
        for (int ks = 0; ks < 4; ks++) {
            uint32_t a[4][4], b[4][2];
#pragma unroll
            for (int mt = 0; mt < 4; mt++) {
                const uint32_t* p = As + (wm * 64 + mt * 16 + tg) * ROWPITCH + ks * 8 + tig;
                a[mt][0] = p[0];
                a[mt][1] = p[8 * ROWPITCH];
                a[mt][2] = p[4];
                a[mt][3] = p[8 * ROWPITCH + 4];
            }
#pragma unroll
            for (int nt = 0; nt < 4; nt++) {
                const uint32_t* p = Bs + (wn * 32 + nt * 8 + tg) * ROWPITCH + ks * 8 + tig;
                b[nt][0] = p[0];
                b[nt][1] = p[4];
            }
#pragma unroll
            for (int mt = 0; mt < 4; mt++)
#pragma unroll
                for (int nt = 0; nt < 4; nt++)
                    mma_tf32_16x8x8(d[mt][nt], a[mt], b[nt]);
        }

        if (c + 2 < NC) {
            __syncthreads();
            issue_chunk(c + 2);
        }
    }

    bool is_l = (nbase < 256);
    float* Y = is_l ? xl : xr;
    const float* bias = is_l ? bl : br;
    int colb = nbase & 255;
#pragma unroll
    for (int mt = 0; mt < 4; mt++) {
        int r0 = row0 + wm * 64 + mt * 16 + tg;
#pragma unroll
        for (int nt = 0; nt < 4; nt++) {
            int col = colb + wn * 32 + nt * 8 + 2 * tig;
            float2 bv = *(const float2*)&bias[col];
            if (r0 < n)
                *(float2*)&Y[(size_t)r0 * 256 + col] =
                    make_float2(d[mt][nt][0] + bv.x, d[mt][nt][1] + bv.y);
            if (r0 + 8 < n)
                *(float2*)&Y[(size_t)(r0 + 8) * 256 + col] =
                    make_float2(d[mt][nt][2] + bv.x, d[mt][nt][3] + bv.y);
        }
    }
}

// build WT[512,K] K-major from Wl/Wr [K,256]; pre-round to tf32
__global__ void build_wt_kernel(const float* __restrict__ Wl, const float* __restrict__ Wr,
                                float* __restrict__ WT, int K) {
    int idx = blockIdx.x * blockDim.x + threadIdx.x;
    if (idx >= 512 * K) return;
    int nrow = idx / K, k = idx - nrow * K;
    float v = (nrow < 256) ? Wl[k * 256 + nrow] : Wr[k * 256 + (nrow - 256)];
    WT[idx] = round_tf32(v);
}

// ---------------- encoder (output tf32-rounded) ----------------
__global__ void enc_kernel(const float* __restrict__ x, const float* __restrict__ W,
                           const float* __restrict__ b, float* __restrict__ h0) {
    int idx = blockIdx.x * blockDim.x + threadIdx.x;
    if (idx >= NN * 64) return;
    int i = idx >> 6;
    int c = idx & 63;
    float acc = b[c];
#pragma unroll
    for (int k = 0; k < 8; k++) acc += x[i * 8 + k] * W[k * 64 + c];
    h0[idx] = round_tf32(fmaxf(acc, 0.f));
}

// ---------------- shared edge-aggregation core (one warp per dst node) ----------------
struct EdgeOut { float o[8]; };

__device__ __forceinline__ EdgeOut edge_aggregate(
    const float* __restrict__ xl, const float* __restrict__ xr,
    const float* __restrict__ We, const float* __restrict__ att,
    const int* __restrict__ rowptr,
    const int* __restrict__ csrc, const float* __restrict__ cea,
    const float* __restrict__ bias, int d, int lane) {
    int c0 = lane * 8;

    float4 xr0 = *(const float4*)&xr[d * 256 + c0];
    float4 xr1 = *(const float4*)&xr[d * 256 + c0 + 4];
    float4 we0 = *(const float4*)&We[c0];
    float4 we1 = *(const float4*)&We[c0 + 4];
    float4 at0 = *(const float4*)&att[c0];
    float4 at1 = *(const float4*)&att[c0 + 4];

    int beg = rowptr[d], end = rowptr[d + 1];
    float m = -INFINITY, den = 0.f;
    float acc[8] = {0.f, 0.f, 0.f, 0.f, 0.f, 0.f, 0.f, 0.f};

    int s_nxt = 0; float ea_nxt = 0.f;
    if (beg < end) { s_nxt = csrc[beg]; ea_nxt = cea[beg]; }

    for (int p = beg; p < end; p++) {
        int s = s_nxt; float ea = ea_nxt;
        if (p + 1 < end) { s_nxt = csrc[p + 1]; ea_nxt = cea[p + 1]; }

        float4 a0 = *(const float4*)&xl[s * 256 + c0];
        float4 a1 = *(const float4*)&xl[s * 256 + c0 + 4];

        float v0 = a0.x + xr0.x + ea * we0.x;
        float v1 = a0.y + xr0.y + ea * we0.y;
        float v2 = a0.z + xr0.z + ea * we0.z;
        float v3 = a0.w + xr0.w + ea * we0.w;
        float v4 = a1.x + xr1.x + ea * we1.x;
        float v5 = a1.y + xr1.y + ea * we1.y;
        float v6 = a1.z + xr1.z + ea * we1.z;
        float v7 = a1.w + xr1.w + ea * we1.w;
        v0 = (v0 > 0.f) ? v0 : 0.2f * v0;
        v1 = (v1 > 0.f) ? v1 : 0.2f * v1;
        v2 = (v2 > 0.f) ? v2 : 0.2f * v2;
        v3 = (v3 > 0.f) ? v3 : 0.2f * v3;
        v4 = (v4 > 0.f) ? v4 : 0.2f * v4;
        v5 = (v5 > 0.f) ? v5 : 0.2f * v5;
        v6 = (v6 > 0.f) ? v6 : 0.2f * v6;
        v7 = (v7 > 0.f) ? v7 : 0.2f * v7;

        float part = v0 * at0.x + v1 * at0.y + v2 * at0.z + v3 * at0.w
                   + v4 * at1.x + v5 * at1.y + v6 * at1.z + v7 * at1.w;
        part += __shfl_xor_sync(0xffffffffu, part, 1);
        part += __shfl_xor_sync(0xffffffffu, part, 2);
        part += __shfl_xor_sync(0xffffffffu, part, 4);
        float l = part;

        float m_new = fmaxf(m, l);
        float scale = __expf(m - m_new);
        float w = __expf(l - m_new);
        den = den * scale + w;
        acc[0] = acc[0] * scale + w * a0.x;
        acc[1] = acc[1] * scale + w * a0.y;
        acc[2] = acc[2] * scale + w * a0.z;
        acc[3] = acc[3] * scale + w * a0.w;
        acc[4] = acc[4] * scale + w * a1.x;
        acc[5] = acc[5] * scale + w * a1.y;
        acc[6] = acc[6] * scale + w * a1.z;
        acc[7] = acc[7] * scale + w * a1.w;
        m = m_new;
    }

    float inv = 1.f / (den + 1e-16f);
    float4 b0 = *(const float4*)&bias[c0];
    float4 b1 = *(const float4*)&bias[c0 + 4];
    EdgeOut r;
    r.o[0] = fmaxf(acc[0] * inv + b0.x, 0.f);
    r.o[1] = fmaxf(acc[1] * inv + b0.y, 0.f);
    r.o[2] = fmaxf(acc[2] * inv + b0.z, 0.f);
    r.o[3] = fmaxf(acc[3] * inv + b0.w, 0.f);
    r.o[4] = fmaxf(acc[4] * inv + b1.x, 0.f);
    r.o[5] = fmaxf(acc[5] * inv + b1.y, 0.f);
    r.o[6] = fmaxf(acc[6] * inv + b1.z, 0.f);
    r.o[7] = fmaxf(acc[7] * inv + b1.w, 0.f);
    return r;
}

// layer 1: write h1 (tf32-rounded, feeds the next GEMM)
__global__ void __launch_bounds__(256)
edge_fused_kernel(const float* __restrict__ xl, const float* __restrict__ xr,
                  const float* __restrict__ We, const float* __restrict__ att,
                  const int* __restrict__ rowptr,
                  const int* __restrict__ csrc, const float* __restrict__ cea,
                  const float* __restrict__ bias, float* __restrict__ h_out) {
    int d = blockIdx.x * 8 + (threadIdx.x >> 5);
    int lane = threadIdx.x & 31;
    if (d >= NN) return;
    EdgeOut r = edge_aggregate(xl, xr, We, att, rowptr, csrc, cea, bias, d, lane);
    int c0 = lane * 8;
#pragma unroll
    for (int i = 0; i < 8; i++) r.o[i] = round_tf32(r.o[i]);
    *(float4*)&h_out[d * 256 + c0]     = make_float4(r.o[0], r.o[1], r.o[2], r.o[3]);
    *(float4*)&h_out[d * 256 + c0 + 4] = make_float4(r.o[4], r.o[5], r.o[6], r.o[7]);
}

// layer 2: fused mean-pool — no h1 write/read.
__global__ void __launch_bounds__(256)
edge_pool_kernel(const float* __restrict__ xl, const float* __restrict__ xr,
                 const float* __restrict__ We, const float* __restrict__ att,
                 const int* __restrict__ rowptr,
                 const int* __restrict__ csrc, const float* __restrict__ cea,
                 const float* __restrict__ bias, const int* __restrict__ batch,
                 float* __restrict__ sums, float* __restrict__ cnt) {
    __shared__ float p0[256], p1[256];
    __shared__ float c0s[2];
    __shared__ int gids[2];
    int t = threadIdx.x;
    int warp = t >> 5, lane = t & 31;
    int d0 = blockIdx.x * 8;
    int d = d0 + warp;

    if (t == 0) {
        int dl = d0 + 7; if (dl >= NN) dl = NN - 1;
        gids[0] = batch[d0 < NN ? d0 : NN - 1];
        gids[1] = batch[dl];
        c0s[0] = 0.f; c0s[1] = 0.f;
    }
    p0[t] = 0.f; p1[t] = 0.f;
    __syncthreads();

    if (d < NN) {
        EdgeOut r = edge_aggregate(xl, xr, We, att, rowptr, csrc, cea, bias, d, lane);
        int b = batch[d];
        int c0 = lane * 8;
        if (b == gids[0]) {
#pragma unroll
            for (int i = 0; i < 8; i++) atomicAdd(&p0[c0 + i], r.o[i]);
            if (lane == 0) atomicAdd(&c0s[0], 1.f);
        } else if (b == gids[1]) {
#pragma unroll
            for (int i = 0; i < 8; i++) atomicAdd(&p1[c0 + i], r.o[i]);
            if (lane == 0) atomicAdd(&c0s[1], 1.f);
        } else {
            red4(&sums[b * 256 + c0], r.o[0], r.o[1], r.o[2], r.o[3]);
            red4(&sums[b * 256 + c0 + 4], r.o[4], r.o[5], r.o[6], r.o[7]);
            if (lane == 0) atomicAdd(&cnt[b], 1.f);
        }
    }
    __syncthreads();

    int g0 = gids[0], g1 = gids[1];
    if (t < 64) {
        float4 v = *(const float4*)&p0[t * 4];
        red4(&sums[g0 * 256 + t * 4], v.x, v.y, v.z, v.w);
    } else if (t < 128 && g1 != g0) {
        int u = t - 64;
        float4 v = *(const float4*)&p1[u * 4];
        red4(&sums[g1 * 256 + u * 4], v.x, v.y, v.z, v.w);
    }
    if (t == 128) atomicAdd(&cnt[g0], c0s[0]);
    if (t == 129 && g1 != g0) atomicAdd(&cnt[g1], c0s[1]);
}

// ---------------- MLP head (also re-zeroes sums/cnt for next replay) ----------------
__global__ void head_kernel(float* __restrict__ sums, float* __restrict__ cnt,
                            const float* __restrict__ Wp1, const float* __restrict__ bp1,
                            const float* __restrict__ lng, const float* __restrict__ lnb,
                            const float* __restrict__ Wp2, const float* __restrict__ bp2,
                            const float* __restrict__ Wh, const float* __restrict__ bh,
                            float* __restrict__ out) {
    __shared__ float pool[256];
    __shared__ float pbuf[128];
    __shared__ float qbuf[64];
    __shared__ float redbuf[4];
    int g = blockIdx.x, t = threadIdx.x;
    float cn = fmaxf(cnt[g], 1.f);
    pool[t] = sums[g * 256 + t] / cn;
    pool[t + 128] = sums[g * 256 + 128 + t] / cn;
    sums[g * 256 + t] = 0.f;
    sums[g * 256 + 128 + t] = 0.f;
    if (t == 0) cnt[g] = 0.f;
    __syncthreads();

    float acc = bp1[t];
#pragma unroll 4
    for (int k = 0; k < 256; k++) acc += pool[k] * Wp1[k * 128 + t];

    float s = acc;
#pragma unroll
    for (int o = 16; o > 0; o >>= 1) s += __shfl_xor_sync(0xffffffffu, s, o);
    if ((t & 31) == 0) redbuf[t >> 5] = s;
    __syncthreads();
    float mu = (redbuf[0] + redbuf[1] + redbuf[2] + redbuf[3]) * (1.f / 128.f);
    __syncthreads();

    float dv = (acc - mu) * (acc - mu);
#pragma unroll
    for (int o = 16; o > 0; o >>= 1) dv += __shfl_xor_sync(0xffffffffu, dv, o);
    if ((t & 31) == 0) redbuf[t >> 5] = dv;
    __syncthreads();
    float var = (redbuf[0] + redbuf[1] + redbuf[2] + redbuf[3]) * (1.f / 128.f);

    float v = (acc - mu) * rsqrtf(var + 1e-5f) * lng[t] + lnb[t];
    pbuf[t] = fmaxf(v, 0.f);
    __syncthreads();

    if (t < 64) {
        float a = bp2[t];
#pragma unroll 4
        for (int k = 0; k < 128; k++) a += pbuf[k] * Wp2[k * 64 + t];
        qbuf[t] = fmaxf(a, 0.f);
    }
    __syncthreads();

    if (t < 32) {
        float a = qbuf[t] * Wh[t] + qbuf[t + 32] * Wh[t + 32];
#pragma unroll
        for (int o = 16; o > 0; o >>= 1) a += __shfl_xor_sync(0xffffffffu, a, o);
        if (t == 0) out[g] = a + bh[0];
    }
}

// ---------------- launch ----------------
static const int MMA_SMEM = 2 * STAGEF * 4;

extern "C" void kernel_launch(void* const* d_in, const int* in_sizes, int n_in,
                              void* d_out, int out_size) {
    const float* x       = (const float*)d_in[0];
    const float* eattr   = (const float*)d_in[1];
    const int*   src     = (const int*)d_in[2];
    const int*   dst     = (const int*)d_in[3];
    const int*   batch   = (const int*)d_in[4];
    const float* W_enc   = (const float*)d_in[5];
    const float* b_enc   = (const float*)d_in[6];
    const float* g1_Wl   = (const float*)d_in[7];
    const float* g1_bl   = (const float*)d_in[8];
    const float* g1_Wr   = (const float*)d_in[9];
    const float* g1_br   = (const float*)d_in[10];
    const float* g1_We   = (const float*)d_in[11];
    const float* g1_att  = (const float*)d_in[12];
    const float* g1_bias = (const float*)d_in[13];
    const float* g2_Wl   = (const float*)d_in[14];
    const float* g2_bl   = (const float*)d_in[15];
    const float* g2_Wr   = (const float*)d_in[16];
    const float* g2_br   = (const float*)d_in[17];
    const float* g2_We   = (const float*)d_in[18];
    const float* g2_att  = (const float*)d_in[19];
    const float* g2_bias = (const float*)d_in[20];
    const float* W_p1    = (const float*)d_in[21];
    const float* b_p1    = (const float*)d_in[22];
    const float* ln_g    = (const float*)d_in[23];
    const float* ln_b    = (const float*)d_in[24];
    const float* W_p2    = (const float*)d_in[25];
    const float* b_p2    = (const float*)d_in[26];
    const float* W_head  = (const float*)d_in[27];
    const float* b_head  = (const float*)d_in[28];
    float* out = (float*)d_out;

    float *h0, *xl, *xr, *h1, *sums, *cnt, *wt, *cea;
    int *rowptr, *cnts, *cursor, *csrc, *bsums;
    cudaGetSymbolAddress((void**)&h0,     g_h0);
    cudaGetSymbolAddress((void**)&xl,     g_xl);
    cudaGetSymbolAddress((void**)&xr,     g_xr);
    cudaGetSymbolAddress((void**)&h1,     g_h1);
    cudaGetSymbolAddress((void**)&sums,   g_sums);
    cudaGetSymbolAddress((void**)&cnt,    g_cnt);
    cudaGetSymbolAddress((void**)&wt,     g_wt);
    cudaGetSymbolAddress((void**)&rowptr, g_rowptr);
    cudaGetSymbolAddress((void**)&cnts,   g_cnts);
    cudaGetSymbolAddress((void**)&cursor, g_cursor);
    cudaGetSymbolAddress((void**)&csrc,   g_csrc);
    cudaGetSymbolAddress((void**)&cea,    g_cea);
    cudaGetSymbolAddress((void**)&bsums,  g_bsums);

    cudaFuncSetAttribute(mma_lr_kernel<64>,
                         cudaFuncAttributeMaxDynamicSharedMemorySize, MMA_SMEM);
    cudaFuncSetAttribute(mma_lr_kernel<256>,
                         cudaFuncAttributeMaxDynamicSharedMemorySize, MMA_SMEM);

    const int MT = (NN + 127) / 128;
    dim3 gemm_grid(4, MT);               // strip-major: siblings share A tile in L2
    const int NB_SCAN = (NN + 1023) / 1024;
    const int EW_GRID = (NN + 7) / 8;

    // harness adds 2 launches before these; ncu -s 5 -c 1 captures my index 3.
    enc_kernel<<<(NN * 64 + 255) / 256, 256>>>(x, W_enc, b_enc, h0);                   // 0
    build_wt_kernel<<<(512 * 64 + 255) / 256, 256>>>(g1_Wl, g1_Wr, wt, 64);            // 1
    hist_kernel<<<(EE + 255) / 256, 256>>>(dst, cnts);                                 // 2
    mma_lr_kernel<64><<<gemm_grid, 256, MMA_SMEM>>>(h0, wt, g1_bl, g1_br, xl, xr, NN); // 3 <- profiled
    scan1_kernel<<<NB_SCAN, 1024>>>(cnts, rowptr, bsums);                              // 4
    scan2_kernel<<<1, 128>>>(bsums, NB_SCAN);                                          // 5
    scan3_kernel<<<NB_SCAN, 1024>>>(rowptr, bsums, cursor);                            // 6
    fillcol_kernel<<<(EE + 255) / 256, 256>>>(dst, src, eattr, cursor, csrc, cea);     // 7

    edge_fused_kernel<<<EW_GRID, 256>>>(xl, xr, g1_We, g1_att,
                                        rowptr, csrc, cea, g1_bias, h1);

    build_wt_kernel<<<(512 * 256 + 255) / 256, 256>>>(g2_Wl, g2_Wr, wt, 256);
    mma_lr_kernel<256><<<gemm_grid, 256, MMA_SMEM>>>(h1, wt, g2_bl, g2_br, xl, xr, NN);
    edge_pool_kernel<<<EW_GRID, 256>>>(xl, xr, g2_We, g2_att,
                                       rowptr, csrc, cea, g2_bias, batch, sums, cnt);

    head_kernel<<<GG, 128>>>(sums, cnt, W_p1, b_p1, ln_g, ln_b, W_p2, b_p2, W_head, b_head, out);
}